// round 6
// baseline (speedup 1.0000x reference)
#include <cuda_runtime.h>
#include <math.h>

// ---------------- problem constants ----------------
#define BB    128
#define SS    256
#define LLQ   10
#define TAGS  32
#define STARTT 30
#define ENDT   31
#define WDIM  100
#define CDIM  30
#define FILT  30
#define HH    100
#define LSTM_IN 130
#define G4    400
#define NEGV  (-10000.0f)

typedef unsigned long long ull;

// ---------------- scratch ----------------
__device__ float g_T  [100*3*FILT];
__device__ float g_x  [BB*SS*LSTM_IN];
__device__ float g_xw [2][BB*SS*G4];
__device__ float g_hcat[BB*SS*2*HH];
__device__ float g_em [BB*SS*TAGS];
__device__ float g_res[BB];

// ---------------- helpers ----------------
__device__ __forceinline__ float sigf(float x) {
    return __fdividef(1.0f, 1.0f + __expf(-x));
}
__device__ __forceinline__ float tanhf_fast(float x) {
    float e = __expf(-2.0f * fabsf(x));
    float t = __fdividef(1.0f - e, 1.0f + e);
    return copysignf(t, x);
}
__device__ __forceinline__ ull ffma2(ull a, ull b, ull c) {
    ull d;
    asm("fma.rn.f32x2 %0, %1, %2, %3;" : "=l"(d) : "l"(a), "l"(b), "l"(c));
    return d;
}
__device__ __forceinline__ ull splat2(float x) {
    ull d; asm("mov.b64 %0, {%1, %1};" : "=l"(d) : "f"(x)); return d;
}
__device__ __forceinline__ ull pack2(float lo, float hi) {
    ull d; asm("mov.b64 %0, {%1, %2};" : "=l"(d) : "f"(lo), "f"(hi)); return d;
}
__device__ __forceinline__ float2 unpack2(ull v) {
    float2 r; asm("mov.b64 {%0, %1}, %2;" : "=f"(r.x), "=f"(r.y) : "l"(v)); return r;
}

// ---------------- K0: conv table ----------------
__global__ void k_table(const float* __restrict__ char_emb,
                        const float* __restrict__ conv_w)
{
    __shared__ float ce[CDIM];
    int c = blockIdx.x;
    int t = threadIdx.x;
    if (t < CDIM) ce[t] = char_emb[c*CDIM + t];
    __syncthreads();
    int k = t / FILT, f = t % FILT;
    float s = 0.0f;
    #pragma unroll
    for (int d = 0; d < CDIM; d++) s += ce[d] * conv_w[f*90 + k*CDIM + d];
    g_T[c*90 + k*FILT + f] = s;
}

// ---------------- K1: word-emb gather + char maxpool ----------------
__global__ void k_embed(const float* __restrict__ word_emb,
                        const float* __restrict__ conv_b,
                        const int*   __restrict__ word_x,
                        const int*   __restrict__ char_x)
{
    __shared__ float ts[9000];
    int tid = threadIdx.x;
    for (int i = tid; i < 9000; i += 256) ts[i] = g_T[i];
    __syncthreads();

    int lane = tid & 31;
    int token = blockIdx.x * 8 + (tid >> 5);

    int w = word_x[token];
    for (int i = lane; i < WDIM; i += 32)
        g_x[(size_t)token*LSTM_IN + i] = word_emb[(size_t)w*WDIM + i];

    int cval = (lane < LLQ) ? char_x[(size_t)token*LLQ + lane] : 0;
    int f2 = (lane < FILT) ? lane : 0;

    float best = -1e30f;
    #pragma unroll
    for (int p = 0; p < 12; p++) {
        float s = 0.0f;
        #pragma unroll
        for (int k = 0; k < 3; k++) {
            int q = p + k - 2;
            if (q >= 0 && q < LLQ) {
                int cq = __shfl_sync(0xffffffffu, cval, q);
                s += ts[cq*90 + k*FILT + f2];
            }
        }
        best = fmaxf(best, s);
    }
    if (lane < FILT)
        g_x[(size_t)token*LSTM_IN + WDIM + lane] = best + conv_b[lane];
}

// ---------------- K2: xw GEMM (unchanged) ----------------
__global__ void k_xw(const float* __restrict__ wih_f, const float* __restrict__ bih_f, const float* __restrict__ bhh_f,
                     const float* __restrict__ wih_b, const float* __restrict__ bih_b, const float* __restrict__ bhh_b)
{
    int dir = blockIdx.z;
    const float* wih = dir ? wih_b : wih_f;
    const float* bih = dir ? bih_b : bih_f;
    const float* bhh = dir ? bhh_b : bhh_f;
    float* outp = g_xw[dir];

    __shared__ float As[16*68];
    __shared__ float Bs[16*68];

    int m0 = blockIdx.x * 64;
    int n0 = blockIdx.y * 64;
    int tid = threadIdx.x;
    int lr = tid >> 2;
    int lk = (tid & 3) * 4;
    int mbase = (tid >> 5) * 8;
    int nb = (tid & 31) * 2;

    ull acc[4][2] = {};

    for (int k0 = 0; k0 < 144; k0 += 16) {
        #pragma unroll
        for (int i = 0; i < 4; i++) {
            int k = k0 + lk + i;
            As[(lk+i)*68 + lr] = (k < LSTM_IN) ? g_x[(size_t)(m0+lr)*LSTM_IN + k] : 0.0f;
            Bs[(lk+i)*68 + lr] = (k < LSTM_IN && (n0+lr) < G4) ? wih[(size_t)(n0+lr)*LSTM_IN + k] : 0.0f;
        }
        __syncthreads();
        #pragma unroll
        for (int kk = 0; kk < 16; kk++) {
            ulonglong2 aA = *(const ulonglong2*)&As[kk*68 + mbase];
            ulonglong2 aB = *(const ulonglong2*)&As[kk*68 + mbase + 4];
            float2 bv = *(const float2*)&Bs[kk*68 + nb];
            ull s0 = splat2(bv.x), s1 = splat2(bv.y);
            acc[0][0] = ffma2(aA.x, s0, acc[0][0]); acc[0][1] = ffma2(aA.x, s1, acc[0][1]);
            acc[1][0] = ffma2(aA.y, s0, acc[1][0]); acc[1][1] = ffma2(aA.y, s1, acc[1][1]);
            acc[2][0] = ffma2(aB.x, s0, acc[2][0]); acc[2][1] = ffma2(aB.x, s1, acc[2][1]);
            acc[3][0] = ffma2(aB.y, s0, acc[3][0]); acc[3][1] = ffma2(aB.y, s1, acc[3][1]);
        }
        __syncthreads();
    }

    int n = n0 + nb;
    if (n < G4) {
        float bn0 = bih[n] + bhh[n];
        float bn1 = bih[n+1] + bhh[n+1];
        #pragma unroll
        for (int i = 0; i < 4; i++) {
            float2 lo = unpack2(acc[i][0]);
            float2 hi = unpack2(acc[i][1]);
            size_t r0 = (size_t)(m0 + mbase + 2*i);
            *(float2*)&outp[r0*G4 + n]     = make_float2(lo.x + bn0, hi.x + bn1);
            *(float2*)&outp[(r0+1)*G4 + n] = make_float2(lo.y + bn0, hi.y + bn1);
        }
    }
}

// ---------------- K3: LSTM recurrence — split-K x2, w[26] in regs ----------------
// 128 blocks (dir x batch-pair), 832 threads.
// Warps 0..12 (t<416): k-half 0 (k 0..51); warps 13..25 (t>=416): k-half 1 (k 52..99).
// Thread owns gate row g = (half? t-416 : t), active when g<400.
// Partial gate sums combined in shared by the activation phase.
__global__ void __launch_bounds__(832, 1) k_lstm(const float* __restrict__ whh_f,
                                                 const float* __restrict__ whh_b)
{
    __shared__ __align__(16) float h0[HH];
    __shared__ __align__(16) float h1[HH];
    __shared__ float p0[800];     // batch b0 partials  [half*400 + g]
    __shared__ float p1[800];     // batch b0+1 partials

    int t = threadIdx.x;
    int half = (t >= 416);
    int g = half ? (t - 416) : t;
    bool active = (g < 400);

    int dir = blockIdx.x >> 6;
    int b0  = (blockIdx.x & 63) * 2;

    const float* whh = dir ? whh_b : whh_f;
    const float* xw  = g_xw[dir];

    ull w[26];
    if (active) {
        const ulonglong2* row = (const ulonglong2*)(whh + (size_t)g*HH + half*52);
        if (!half) {
            #pragma unroll
            for (int i = 0; i < 13; i++) { ulonglong2 v = row[i]; w[2*i] = v.x; w[2*i+1] = v.y; }
        } else {
            #pragma unroll
            for (int i = 0; i < 12; i++) { ulonglong2 v = row[i]; w[2*i] = v.x; w[2*i+1] = v.y; }
        }
    }

    if (t < HH) { h0[t] = 0.0f; h1[t] = 0.0f; }
    int r_act = (t < 200) ? (t / HH) : 0;
    int j_act = (t < 200) ? (t % HH) : 0;
    float c_reg = 0.0f;
    __syncthreads();

    const ulonglong2* hp0 = (const ulonglong2*)h0;
    const ulonglong2* hp1 = (const ulonglong2*)h1;

    const float* xp0 = xw + (size_t)b0    *SS*G4 + g;
    const float* xp1 = xw + (size_t)(b0+1)*SS*G4 + g;

    int s0 = dir ? (SS-1) : 0;
    float xa = 0.0f, xb = 0.0f;
    if (!half && active) { xa = xp0[s0*G4]; xb = xp1[s0*G4]; }

    for (int step = 0; step < SS; step++) {
        int sidx = dir ? (SS-1-step) : step;

        if (active) {
            ull a00, a01 = 0ULL, a10, a11 = 0ULL;
            if (!half) {
                a00 = pack2(xa, 0.0f);
                a10 = pack2(xb, 0.0f);
                #pragma unroll
                for (int i = 0; i < 13; i++) {
                    ulonglong2 hv0 = hp0[i];
                    ulonglong2 hv1 = hp1[i];
                    a00 = ffma2(w[2*i],   hv0.x, a00);
                    a01 = ffma2(w[2*i+1], hv0.y, a01);
                    a10 = ffma2(w[2*i],   hv1.x, a10);
                    a11 = ffma2(w[2*i+1], hv1.y, a11);
                }
                if (step + 1 < SS) {
                    int sn = dir ? (SS-2-step) : (step+1);
                    xa = xp0[sn*G4];
                    xb = xp1[sn*G4];
                }
            } else {
                a00 = 0ULL; a10 = 0ULL;
                #pragma unroll
                for (int i = 0; i < 12; i++) {
                    ulonglong2 hv0 = hp0[13+i];
                    ulonglong2 hv1 = hp1[13+i];
                    a00 = ffma2(w[2*i],   hv0.x, a00);
                    a01 = ffma2(w[2*i+1], hv0.y, a01);
                    a10 = ffma2(w[2*i],   hv1.x, a10);
                    a11 = ffma2(w[2*i+1], hv1.y, a11);
                }
            }
            float2 e0 = unpack2(a00), o0 = unpack2(a01);
            float2 e1 = unpack2(a10), o1 = unpack2(a11);
            p0[half*400 + g] = (e0.x + o0.x) + (e0.y + o0.y);
            p1[half*400 + g] = (e1.x + o1.x) + (e1.y + o1.y);
        }
        __syncthreads();

        if (t < 200) {
            const float* pr = r_act ? p1 : p0;
            float gi = pr[          j_act] + pr[400 +          j_act];
            float gf = pr[  HH    + j_act] + pr[400 +   HH   + j_act];
            float gg = pr[2*HH    + j_act] + pr[400 + 2*HH   + j_act];
            float go = pr[3*HH    + j_act] + pr[400 + 3*HH   + j_act];
            float si = sigf(gi), sf = sigf(gf), so = sigf(go);
            c_reg = sf*c_reg + si*tanhf_fast(gg);
            float h = so*tanhf_fast(c_reg);
            ((r_act == 0) ? h0 : h1)[j_act] = h;
            g_hcat[((size_t)(b0 + r_act)*SS + sidx)*(2*HH) + dir*HH + j_act] = h;
        }
        __syncthreads();
    }
}

// ---------------- K4: emission GEMM (unchanged) ----------------
__global__ void k_emission(const float* __restrict__ proj_w, const float* __restrict__ proj_b)
{
    __shared__ float As[8*68];
    __shared__ float Bs[8*32];
    int tid = threadIdx.x;
    int m0 = blockIdx.x * 64;
    int lr = tid >> 2;
    int lk = (tid & 3) * 2;
    int mbase = (tid >> 5) * 8;
    int n = tid & 31;

    ull acc[4] = {};

    for (int k0 = 0; k0 < 200; k0 += 8) {
        #pragma unroll
        for (int i = 0; i < 2; i++)
            As[(lk+i)*68 + lr] = g_hcat[(size_t)(m0+lr)*200 + k0 + lk + i];
        {
            int kq = tid >> 5, nn = tid & 31;
            Bs[kq*32 + nn] = proj_w[nn*200 + k0 + kq];
        }
        __syncthreads();
        #pragma unroll
        for (int kk = 0; kk < 8; kk++) {
            ulonglong2 aA = *(const ulonglong2*)&As[kk*68 + mbase];
            ulonglong2 aB = *(const ulonglong2*)&As[kk*68 + mbase + 4];
            ull s = splat2(Bs[kk*32 + n]);
            acc[0] = ffma2(aA.x, s, acc[0]);
            acc[1] = ffma2(aA.y, s, acc[1]);
            acc[2] = ffma2(aB.x, s, acc[2]);
            acc[3] = ffma2(aB.y, s, acc[3]);
        }
        __syncthreads();
    }

    float pb = proj_b[n];
    #pragma unroll
    for (int i = 0; i < 4; i++) {
        float2 v = unpack2(acc[i]);
        g_em[(size_t)(m0 + mbase + 2*i    )*TAGS + n] = v.x + pb;
        g_em[(size_t)(m0 + mbase + 2*i + 1)*TAGS + n] = v.y + pb;
    }
}

// ---------------- K5: CRF forward — 4 warps split the i-dimension ----------------
// grid 128 (one block per batch row), 128 threads.
// Warp q: partial logsumexp over i in [8q, 8q+8) for all 32 j.
// Warp 0 merges 4 partials (rescaled), applies emission + mask, updates la_s.
__global__ void k_crf(const float* __restrict__ trans,
                      const int* __restrict__ y, const int* __restrict__ mask)
{
    __shared__ float la_s[TAGS];
    __shared__ float pm[4*TAGS];
    __shared__ float ps[4*TAGS];
    __shared__ float red[128];
    __shared__ float sh_total;

    int b = blockIdx.x;
    int tid = threadIdx.x;
    int j = tid & 31;
    int q = tid >> 5;

    float tr[8];
    #pragma unroll
    for (int ii = 0; ii < 8; ii++) tr[ii] = trans[(8*q + ii)*TAGS + j];

    if (tid < TAGS) la_s[tid] = (tid == STARTT) ? 0.0f : NEGV;
    __syncthreads();

    const float* em = g_em + (size_t)b*SS*TAGS;
    const int* mk = mask + b*SS;

    float e_next = 0.0f;
    int   m_next = 0;
    if (q == 0) { e_next = em[j]; m_next = mk[0]; }

    for (int s = 0; s < SS; s++) {
        float v[8];
        #pragma unroll
        for (int ii = 0; ii < 8; ii++) v[ii] = la_s[8*q + ii] + tr[ii];

        float m4[4];
        #pragma unroll
        for (int ii = 0; ii < 4; ii++) m4[ii] = fmaxf(v[ii], v[ii+4]);
        float m = fmaxf(fmaxf(m4[0], m4[1]), fmaxf(m4[2], m4[3]));

        float ev[8];
        #pragma unroll
        for (int ii = 0; ii < 8; ii++) ev[ii] = __expf(v[ii] - m);
        float sum = ((ev[0]+ev[4]) + (ev[1]+ev[5])) + ((ev[2]+ev[6]) + (ev[3]+ev[7]));

        pm[q*TAGS + j] = m;
        ps[q*TAGS + j] = sum;
        __syncthreads();

        if (q == 0) {
            float e = e_next;
            int mm = m_next;
            if (s + 1 < SS) { e_next = em[(s+1)*TAGS + j]; m_next = mk[s+1]; }
            float m0 = pm[j], m1 = pm[TAGS+j], m2 = pm[2*TAGS+j], m3 = pm[3*TAGS+j];
            float M = fmaxf(fmaxf(m0, m1), fmaxf(m2, m3));
            float S = ps[j]*__expf(m0-M) + ps[TAGS+j]*__expf(m1-M)
                    + ps[2*TAGS+j]*__expf(m2-M) + ps[3*TAGS+j]*__expf(m3-M);
            float la2 = e + M + __logf(S);
            la_s[j] = mm ? la2 : la_s[j];
        }
        __syncthreads();
    }

    // total = logsumexp(la + trans[:, END])
    if (q == 0) {
        float la = la_s[j] + trans[j*TAGS + ENDT];
        float mv = la;
        #pragma unroll
        for (int o = 16; o > 0; o >>= 1) mv = fmaxf(mv, __shfl_xor_sync(0xffffffffu, mv, o));
        float ex = __expf(la - mv);
        #pragma unroll
        for (int o = 16; o > 0; o >>= 1) ex += __shfl_xor_sync(0xffffffffu, ex, o);
        if (j == 0) sh_total = mv + __logf(ex);
    }

    // gold score over 128 threads
    const int* yb = y + b*SS;
    float sc = 0.0f;
    for (int s = tid; s < SS; s += 128) {
        int cur  = yb[s];
        int prev = s ? yb[s-1] : STARTT;
        float p = em[s*TAGS + cur];
        float tt = trans[prev*TAGS + cur];
        sc += (p + tt) * (float)mk[s];
    }
    red[tid] = sc;
    __syncthreads();
    if (tid < 64) red[tid] += red[tid+64];
    __syncthreads();
    if (tid < 32) {
        float v = red[tid] + red[tid+32];
        #pragma unroll
        for (int o = 16; o > 0; o >>= 1) v += __shfl_xor_sync(0xffffffffu, v, o);
        if (tid == 0) {
            v += trans[yb[SS-1]*TAGS + ENDT];
            g_res[b] = v - sh_total;
        }
    }
}

// ---------------- K6: final reduction ----------------
__global__ void k_final(float* out)
{
    __shared__ float s[BB];
    int t = threadIdx.x;
    s[t] = g_res[t];
    __syncthreads();
    for (int o = 64; o > 0; o >>= 1) {
        if (t < o) s[t] += s[t+o];
        __syncthreads();
    }
    if (t == 0) out[0] = -s[0] / (float)BB;
}

// ---------------- launch ----------------
extern "C" void kernel_launch(void* const* d_in, const int* in_sizes, int n_in,
                              void* d_out, int out_size)
{
    const float* word_emb = (const float*)d_in[0];
    const float* char_emb = (const float*)d_in[1];
    const float* conv_w   = (const float*)d_in[2];
    const float* conv_b   = (const float*)d_in[3];
    const float* wih_f    = (const float*)d_in[4];
    const float* whh_f    = (const float*)d_in[5];
    const float* bih_f    = (const float*)d_in[6];
    const float* bhh_f    = (const float*)d_in[7];
    const float* wih_b    = (const float*)d_in[8];
    const float* whh_b    = (const float*)d_in[9];
    const float* bih_b    = (const float*)d_in[10];
    const float* bhh_b    = (const float*)d_in[11];
    const float* proj_w   = (const float*)d_in[12];
    const float* proj_b   = (const float*)d_in[13];
    const float* trans    = (const float*)d_in[14];
    const int*   word_x   = (const int*)d_in[15];
    const int*   char_x   = (const int*)d_in[16];
    const int*   y        = (const int*)d_in[17];
    const int*   mask     = (const int*)d_in[18];
    float* out = (float*)d_out;

    k_table<<<100, 90>>>(char_emb, conv_w);
    k_embed<<<BB*SS/8, 256>>>(word_emb, conv_b, word_x, char_x);

    dim3 g2(512, 7, 2);
    k_xw<<<g2, 256>>>(wih_f, bih_f, bhh_f, wih_b, bih_b, bhh_b);

    k_lstm<<<128, 832>>>(whh_f, whh_b);

    k_emission<<<BB*SS/64, 256>>>(proj_w, proj_b);

    k_crf<<<BB, 128>>>(trans, y, mask);

    k_final<<<1, BB>>>(out);
}

// round 7
// speedup vs baseline: 1.1930x; 1.1930x over previous
#include <cuda_runtime.h>
#include <math.h>

// ---------------- problem constants ----------------
#define BB    128
#define SS    256
#define LLQ   10
#define TAGS  32
#define STARTT 30
#define ENDT   31
#define WDIM  100
#define CDIM  30
#define FILT  30
#define HH    100
#define LSTM_IN 130
#define G4    400
#define NEGV  (-10000.0f)

typedef unsigned long long ull;

// ---------------- scratch ----------------
__device__ float g_T  [100*3*FILT];
__device__ float g_x  [BB*SS*LSTM_IN];
__device__ float g_xw [2][BB*SS*G4];
__device__ float g_hcat[BB*SS*2*HH];
__device__ float g_em [BB*SS*TAGS];
__device__ float g_res[BB];

// ---------------- helpers ----------------
__device__ __forceinline__ float tanh_hw(float x) {
    float y; asm("tanh.approx.f32 %0, %1;" : "=f"(y) : "f"(x)); return y;
}
__device__ __forceinline__ float sig_hw(float x) {
    return fmaf(0.5f, tanh_hw(0.5f*x), 0.5f);
}
__device__ __forceinline__ ull ffma2(ull a, ull b, ull c) {
    ull d;
    asm("fma.rn.f32x2 %0, %1, %2, %3;" : "=l"(d) : "l"(a), "l"(b), "l"(c));
    return d;
}
__device__ __forceinline__ ull splat2(float x) {
    ull d; asm("mov.b64 %0, {%1, %1};" : "=l"(d) : "f"(x)); return d;
}
__device__ __forceinline__ ull pack2(float lo, float hi) {
    ull d; asm("mov.b64 %0, {%1, %2};" : "=l"(d) : "f"(lo), "f"(hi)); return d;
}
__device__ __forceinline__ float2 unpack2(ull v) {
    float2 r; asm("mov.b64 {%0, %1}, %2;" : "=f"(r.x), "=f"(r.y) : "l"(v)); return r;
}

// ---------------- K0: conv table ----------------
__global__ void k_table(const float* __restrict__ char_emb,
                        const float* __restrict__ conv_w)
{
    __shared__ float ce[CDIM];
    int c = blockIdx.x;
    int t = threadIdx.x;
    if (t < CDIM) ce[t] = char_emb[c*CDIM + t];
    __syncthreads();
    int k = t / FILT, f = t % FILT;
    float s = 0.0f;
    #pragma unroll
    for (int d = 0; d < CDIM; d++) s += ce[d] * conv_w[f*90 + k*CDIM + d];
    g_T[c*90 + k*FILT + f] = s;
}

// ---------------- K1: word-emb gather + char maxpool ----------------
__global__ void k_embed(const float* __restrict__ word_emb,
                        const float* __restrict__ conv_b,
                        const int*   __restrict__ word_x,
                        const int*   __restrict__ char_x)
{
    __shared__ float ts[9000];
    int tid = threadIdx.x;
    for (int i = tid; i < 9000; i += 256) ts[i] = g_T[i];
    __syncthreads();

    int lane = tid & 31;
    int token = blockIdx.x * 8 + (tid >> 5);

    int w = word_x[token];
    for (int i = lane; i < WDIM; i += 32)
        g_x[(size_t)token*LSTM_IN + i] = word_emb[(size_t)w*WDIM + i];

    int cval = (lane < LLQ) ? char_x[(size_t)token*LLQ + lane] : 0;
    int f2 = (lane < FILT) ? lane : 0;

    float best = -1e30f;
    #pragma unroll
    for (int p = 0; p < 12; p++) {
        float s = 0.0f;
        #pragma unroll
        for (int k = 0; k < 3; k++) {
            int q = p + k - 2;
            if (q >= 0 && q < LLQ) {
                int cq = __shfl_sync(0xffffffffu, cval, q);
                s += ts[cq*90 + k*FILT + f2];
            }
        }
        best = fmaxf(best, s);
    }
    if (lane < FILT)
        g_x[(size_t)token*LSTM_IN + WDIM + lane] = best + conv_b[lane];
}

// ---------------- K2: xw GEMM ----------------
__global__ void k_xw(const float* __restrict__ wih_f, const float* __restrict__ bih_f, const float* __restrict__ bhh_f,
                     const float* __restrict__ wih_b, const float* __restrict__ bih_b, const float* __restrict__ bhh_b)
{
    int dir = blockIdx.z;
    const float* wih = dir ? wih_b : wih_f;
    const float* bih = dir ? bih_b : bih_f;
    const float* bhh = dir ? bhh_b : bhh_f;
    float* outp = g_xw[dir];

    __shared__ float As[16*68];
    __shared__ float Bs[16*68];

    int m0 = blockIdx.x * 64;
    int n0 = blockIdx.y * 64;
    int tid = threadIdx.x;
    int lr = tid >> 2;
    int lk = (tid & 3) * 4;
    int mbase = (tid >> 5) * 8;
    int nb = (tid & 31) * 2;

    ull acc[4][2] = {};

    for (int k0 = 0; k0 < 144; k0 += 16) {
        #pragma unroll
        for (int i = 0; i < 4; i++) {
            int k = k0 + lk + i;
            As[(lk+i)*68 + lr] = (k < LSTM_IN) ? g_x[(size_t)(m0+lr)*LSTM_IN + k] : 0.0f;
            Bs[(lk+i)*68 + lr] = (k < LSTM_IN && (n0+lr) < G4) ? wih[(size_t)(n0+lr)*LSTM_IN + k] : 0.0f;
        }
        __syncthreads();
        #pragma unroll
        for (int kk = 0; kk < 16; kk++) {
            ulonglong2 aA = *(const ulonglong2*)&As[kk*68 + mbase];
            ulonglong2 aB = *(const ulonglong2*)&As[kk*68 + mbase + 4];
            float2 bv = *(const float2*)&Bs[kk*68 + nb];
            ull s0 = splat2(bv.x), s1 = splat2(bv.y);
            acc[0][0] = ffma2(aA.x, s0, acc[0][0]); acc[0][1] = ffma2(aA.x, s1, acc[0][1]);
            acc[1][0] = ffma2(aA.y, s0, acc[1][0]); acc[1][1] = ffma2(aA.y, s1, acc[1][1]);
            acc[2][0] = ffma2(aB.x, s0, acc[2][0]); acc[2][1] = ffma2(aB.x, s1, acc[2][1]);
            acc[3][0] = ffma2(aB.y, s0, acc[3][0]); acc[3][1] = ffma2(aB.y, s1, acc[3][1]);
        }
        __syncthreads();
    }

    int n = n0 + nb;
    if (n < G4) {
        float bn0 = bih[n] + bhh[n];
        float bn1 = bih[n+1] + bhh[n+1];
        #pragma unroll
        for (int i = 0; i < 4; i++) {
            float2 lo = unpack2(acc[i][0]);
            float2 hi = unpack2(acc[i][1]);
            size_t r0 = (size_t)(m0 + mbase + 2*i);
            *(float2*)&outp[r0*G4 + n]     = make_float2(lo.x + bn0, hi.x + bn1);
            *(float2*)&outp[(r0+1)*G4 + n] = make_float2(lo.y + bn0, hi.y + bn1);
        }
    }
}

// ---------------- K3: LSTM recurrence — R4 design + HW tanh activations ----------------
// 128 blocks (2 dir x 64 batch-pairs), 400 threads. Thread t = gate row g.
// whh row (100 floats) in 50 ull registers; FFMA2 even/odd-k partial chains.
__global__ void __launch_bounds__(400, 1) k_lstm(const float* __restrict__ whh_f,
                                                 const float* __restrict__ whh_b)
{
    __shared__ __align__(16) float h0[HH];
    __shared__ __align__(16) float h1[HH];
    __shared__ float gate[2*G4];

    int t   = threadIdx.x;
    int dir = blockIdx.x >> 6;
    int b0  = (blockIdx.x & 63) * 2;

    const float* whh = dir ? whh_b : whh_f;
    const float* xw  = g_xw[dir];

    ull w[50];
    {
        const ulonglong2* row = (const ulonglong2*)(whh + (size_t)t*HH);
        #pragma unroll
        for (int i = 0; i < 25; i++) {
            ulonglong2 v = row[i];
            w[2*i]   = v.x;
            w[2*i+1] = v.y;
        }
    }

    if (t < HH) { h0[t] = 0.0f; h1[t] = 0.0f; }
    int r_act = (t < 200) ? (t / HH) : 0;
    int j_act = (t < 200) ? (t % HH) : 0;
    float c_reg = 0.0f;
    __syncthreads();

    const ulonglong2* hp0 = (const ulonglong2*)h0;
    const ulonglong2* hp1 = (const ulonglong2*)h1;

    int s0 = dir ? (SS-1) : 0;
    float xa = xw[((size_t)b0    *SS + s0)*G4 + t];
    float xb = xw[((size_t)(b0+1)*SS + s0)*G4 + t];

    for (int step = 0; step < SS; step++) {
        int sidx = dir ? (SS-1-step) : step;

        ull acc00 = pack2(xa, 0.0f), acc01 = 0ULL;
        ull acc10 = pack2(xb, 0.0f), acc11 = 0ULL;
        #pragma unroll
        for (int i = 0; i < 25; i++) {
            ulonglong2 hv0 = hp0[i];
            ulonglong2 hv1 = hp1[i];
            acc00 = ffma2(w[2*i],   hv0.x, acc00);
            acc01 = ffma2(w[2*i+1], hv0.y, acc01);
            acc10 = ffma2(w[2*i],   hv1.x, acc10);
            acc11 = ffma2(w[2*i+1], hv1.y, acc11);
        }
        if (step + 1 < SS) {
            int snext = dir ? (SS-2-step) : (step+1);
            xa = xw[((size_t)b0    *SS + snext)*G4 + t];
            xb = xw[((size_t)(b0+1)*SS + snext)*G4 + t];
        }

        float2 p0 = unpack2(acc00), q0 = unpack2(acc01);
        float2 p1 = unpack2(acc10), q1 = unpack2(acc11);
        gate[t]      = (p0.x + q0.x) + (p0.y + q0.y);
        gate[G4 + t] = (p1.x + q1.x) + (p1.y + q1.y);
        __syncthreads();

        if (t < 200) {
            const float* gs = gate + r_act*G4;
            float gi = gs[j_act], gf = gs[HH + j_act], gg = gs[2*HH + j_act], go = gs[3*HH + j_act];
            float si = sig_hw(gi), sf = sig_hw(gf), so = sig_hw(go);
            c_reg = sf*c_reg + si*tanh_hw(gg);
            float h = so*tanh_hw(c_reg);
            ((r_act == 0) ? h0 : h1)[j_act] = h;
            g_hcat[((size_t)(b0 + r_act)*SS + sidx)*(2*HH) + dir*HH + j_act] = h;
        }
        __syncthreads();
    }
}

// ---------------- K4: emission GEMM ----------------
__global__ void k_emission(const float* __restrict__ proj_w, const float* __restrict__ proj_b)
{
    __shared__ float As[8*68];
    __shared__ float Bs[8*32];
    int tid = threadIdx.x;
    int m0 = blockIdx.x * 64;
    int lr = tid >> 2;
    int lk = (tid & 3) * 2;
    int mbase = (tid >> 5) * 8;
    int n = tid & 31;

    ull acc[4] = {};

    for (int k0 = 0; k0 < 200; k0 += 8) {
        #pragma unroll
        for (int i = 0; i < 2; i++)
            As[(lk+i)*68 + lr] = g_hcat[(size_t)(m0+lr)*200 + k0 + lk + i];
        {
            int kq = tid >> 5, nn = tid & 31;
            Bs[kq*32 + nn] = proj_w[nn*200 + k0 + kq];
        }
        __syncthreads();
        #pragma unroll
        for (int kk = 0; kk < 8; kk++) {
            ulonglong2 aA = *(const ulonglong2*)&As[kk*68 + mbase];
            ulonglong2 aB = *(const ulonglong2*)&As[kk*68 + mbase + 4];
            ull s = splat2(Bs[kk*32 + n]);
            acc[0] = ffma2(aA.x, s, acc[0]);
            acc[1] = ffma2(aA.y, s, acc[1]);
            acc[2] = ffma2(aB.x, s, acc[2]);
            acc[3] = ffma2(aB.y, s, acc[3]);
        }
        __syncthreads();
    }

    float pb = proj_b[n];
    #pragma unroll
    for (int i = 0; i < 4; i++) {
        float2 v = unpack2(acc[i]);
        g_em[(size_t)(m0 + mbase + 2*i    )*TAGS + n] = v.x + pb;
        g_em[(size_t)(m0 + mbase + 2*i + 1)*TAGS + n] = v.y + pb;
    }
}

// ---------------- K5: CRF forward — 4 warps split the i-dimension ----------------
__global__ void k_crf(const float* __restrict__ trans,
                      const int* __restrict__ y, const int* __restrict__ mask)
{
    __shared__ float la_s[TAGS];
    __shared__ float pm[4*TAGS];
    __shared__ float ps[4*TAGS];
    __shared__ float red[128];
    __shared__ float sh_total;

    int b = blockIdx.x;
    int tid = threadIdx.x;
    int j = tid & 31;
    int q = tid >> 5;

    float tr[8];
    #pragma unroll
    for (int ii = 0; ii < 8; ii++) tr[ii] = trans[(8*q + ii)*TAGS + j];

    if (tid < TAGS) la_s[tid] = (tid == STARTT) ? 0.0f : NEGV;
    __syncthreads();

    const float* em = g_em + (size_t)b*SS*TAGS;
    const int* mk = mask + b*SS;

    float e_next = 0.0f;
    int   m_next = 0;
    if (q == 0) { e_next = em[j]; m_next = mk[0]; }

    for (int s = 0; s < SS; s++) {
        float v[8];
        #pragma unroll
        for (int ii = 0; ii < 8; ii++) v[ii] = la_s[8*q + ii] + tr[ii];

        float m4[4];
        #pragma unroll
        for (int ii = 0; ii < 4; ii++) m4[ii] = fmaxf(v[ii], v[ii+4]);
        float m = fmaxf(fmaxf(m4[0], m4[1]), fmaxf(m4[2], m4[3]));

        float ev[8];
        #pragma unroll
        for (int ii = 0; ii < 8; ii++) ev[ii] = __expf(v[ii] - m);
        float sum = ((ev[0]+ev[4]) + (ev[1]+ev[5])) + ((ev[2]+ev[6]) + (ev[3]+ev[7]));

        pm[q*TAGS + j] = m;
        ps[q*TAGS + j] = sum;
        __syncthreads();

        if (q == 0) {
            float e = e_next;
            int mm = m_next;
            if (s + 1 < SS) { e_next = em[(s+1)*TAGS + j]; m_next = mk[s+1]; }
            float m0 = pm[j], m1 = pm[TAGS+j], m2 = pm[2*TAGS+j], m3 = pm[3*TAGS+j];
            float M = fmaxf(fmaxf(m0, m1), fmaxf(m2, m3));
            float S = ps[j]*__expf(m0-M) + ps[TAGS+j]*__expf(m1-M)
                    + ps[2*TAGS+j]*__expf(m2-M) + ps[3*TAGS+j]*__expf(m3-M);
            float la2 = e + M + __logf(S);
            la_s[j] = mm ? la2 : la_s[j];
        }
        __syncthreads();
    }

    if (q == 0) {
        float la = la_s[j] + trans[j*TAGS + ENDT];
        float mv = la;
        #pragma unroll
        for (int o = 16; o > 0; o >>= 1) mv = fmaxf(mv, __shfl_xor_sync(0xffffffffu, mv, o));
        float ex = __expf(la - mv);
        #pragma unroll
        for (int o = 16; o > 0; o >>= 1) ex += __shfl_xor_sync(0xffffffffu, ex, o);
        if (j == 0) sh_total = mv + __logf(ex);
    }

    const int* yb = y + b*SS;
    float sc = 0.0f;
    for (int s = tid; s < SS; s += 128) {
        int cur  = yb[s];
        int prev = s ? yb[s-1] : STARTT;
        float p = em[s*TAGS + cur];
        float tt = trans[prev*TAGS + cur];
        sc += (p + tt) * (float)mk[s];
    }
    red[tid] = sc;
    __syncthreads();
    if (tid < 64) red[tid] += red[tid+64];
    __syncthreads();
    if (tid < 32) {
        float v = red[tid] + red[tid+32];
        #pragma unroll
        for (int o = 16; o > 0; o >>= 1) v += __shfl_xor_sync(0xffffffffu, v, o);
        if (tid == 0) {
            v += trans[yb[SS-1]*TAGS + ENDT];
            g_res[b] = v - sh_total;
        }
    }
}

// ---------------- K6: final reduction ----------------
__global__ void k_final(float* out)
{
    __shared__ float s[BB];
    int t = threadIdx.x;
    s[t] = g_res[t];
    __syncthreads();
    for (int o = 64; o > 0; o >>= 1) {
        if (t < o) s[t] += s[t+o];
        __syncthreads();
    }
    if (t == 0) out[0] = -s[0] / (float)BB;
}

// ---------------- launch ----------------
extern "C" void kernel_launch(void* const* d_in, const int* in_sizes, int n_in,
                              void* d_out, int out_size)
{
    const float* word_emb = (const float*)d_in[0];
    const float* char_emb = (const float*)d_in[1];
    const float* conv_w   = (const float*)d_in[2];
    const float* conv_b   = (const float*)d_in[3];
    const float* wih_f    = (const float*)d_in[4];
    const float* whh_f    = (const float*)d_in[5];
    const float* bih_f    = (const float*)d_in[6];
    const float* bhh_f    = (const float*)d_in[7];
    const float* wih_b    = (const float*)d_in[8];
    const float* whh_b    = (const float*)d_in[9];
    const float* bih_b    = (const float*)d_in[10];
    const float* bhh_b    = (const float*)d_in[11];
    const float* proj_w   = (const float*)d_in[12];
    const float* proj_b   = (const float*)d_in[13];
    const float* trans    = (const float*)d_in[14];
    const int*   word_x   = (const int*)d_in[15];
    const int*   char_x   = (const int*)d_in[16];
    const int*   y        = (const int*)d_in[17];
    const int*   mask     = (const int*)d_in[18];
    float* out = (float*)d_out;

    k_table<<<100, 90>>>(char_emb, conv_w);
    k_embed<<<BB*SS/8, 256>>>(word_emb, conv_b, word_x, char_x);

    dim3 g2(512, 7, 2);
    k_xw<<<g2, 256>>>(wih_f, bih_f, bhh_f, wih_b, bih_b, bhh_b);

    k_lstm<<<128, 400>>>(whh_f, whh_b);

    k_emission<<<BB*SS/64, 256>>>(proj_w, proj_b);

    k_crf<<<BB, 128>>>(trans, y, mask);

    k_final<<<1, BB>>>(out);
}

// round 10
// speedup vs baseline: 1.3419x; 1.1248x over previous
#include <cuda_runtime.h>
#include <math.h>
#include <stdint.h>

// ---------------- problem constants ----------------
#define BB    128
#define SS    256
#define LLQ   10
#define TAGS  32
#define STARTT 30
#define ENDT   31
#define WDIM  100
#define CDIM  30
#define FILT  30
#define HH    100
#define LSTM_IN 130
#define G4    400
#define NEGV  (-10000.0f)

typedef unsigned long long ull;

// ---------------- scratch ----------------
__device__ float g_T  [100*3*FILT];
__device__ float g_x  [BB*SS*LSTM_IN];
__device__ float g_xw [2][BB*SS*G4];
__device__ float g_hcat[BB*SS*2*HH];
__device__ float g_em [BB*SS*TAGS];
__device__ float g_res[BB];

// ---------------- helpers ----------------
__device__ __forceinline__ float tanh_hw(float x) {
    float y; asm("tanh.approx.f32 %0, %1;" : "=f"(y) : "f"(x)); return y;
}
__device__ __forceinline__ float sig_hw(float x) {
    return fmaf(0.5f, tanh_hw(0.5f*x), 0.5f);
}
__device__ __forceinline__ ull ffma2(ull a, ull b, ull c) {
    ull d;
    asm("fma.rn.f32x2 %0, %1, %2, %3;" : "=l"(d) : "l"(a), "l"(b), "l"(c));
    return d;
}
__device__ __forceinline__ ull splat2(float x) {
    ull d; asm("mov.b64 %0, {%1, %1};" : "=l"(d) : "f"(x)); return d;
}
__device__ __forceinline__ ull pack2(float lo, float hi) {
    ull d; asm("mov.b64 %0, {%1, %2};" : "=l"(d) : "f"(lo), "f"(hi)); return d;
}
__device__ __forceinline__ float2 unpack2(ull v) {
    float2 r; asm("mov.b64 {%0, %1}, %2;" : "=f"(r.x), "=f"(r.y) : "l"(v)); return r;
}
__device__ __forceinline__ float cvt_tf32(float x) {
    uint32_t u;
    asm("cvt.rna.tf32.f32 %0, %1;" : "=r"(u) : "f"(x));
    return __uint_as_float(u);
}
__device__ __forceinline__ void mma_tf32(float* c,
                                         float a0, float a1, float a2, float a3,
                                         float b0, float b1) {
    asm("mma.sync.aligned.m16n8k8.row.col.f32.tf32.tf32.f32 "
        "{%0,%1,%2,%3}, {%4,%5,%6,%7}, {%8,%9}, {%0,%1,%2,%3};"
        : "+f"(c[0]), "+f"(c[1]), "+f"(c[2]), "+f"(c[3])
        : "r"(__float_as_uint(a0)), "r"(__float_as_uint(a1)),
          "r"(__float_as_uint(a2)), "r"(__float_as_uint(a3)),
          "r"(__float_as_uint(b0)), "r"(__float_as_uint(b1)));
}

// ---------------- K0: conv table ----------------
__global__ void k_table(const float* __restrict__ char_emb,
                        const float* __restrict__ conv_w)
{
    __shared__ float ce[CDIM];
    int c = blockIdx.x;
    int t = threadIdx.x;
    if (t < CDIM) ce[t] = char_emb[c*CDIM + t];
    __syncthreads();
    int k = t / FILT, f = t % FILT;
    float s = 0.0f;
    #pragma unroll
    for (int d = 0; d < CDIM; d++) s += ce[d] * conv_w[f*90 + k*CDIM + d];
    g_T[c*90 + k*FILT + f] = s;
}

// ---------------- K1: word-emb gather + char maxpool (32 tokens/block) ----------------
__global__ void k_embed(const float* __restrict__ word_emb,
                        const float* __restrict__ conv_b,
                        const int*   __restrict__ word_x,
                        const int*   __restrict__ char_x)
{
    __shared__ float ts[9000];
    int tid = threadIdx.x;
    for (int i = tid; i < 9000; i += 256) ts[i] = g_T[i];
    __syncthreads();

    int lane = tid & 31;
    int warp = tid >> 5;
    float cb = (lane < FILT) ? conv_b[lane] : 0.0f;

    #pragma unroll
    for (int tk = 0; tk < 4; tk++) {
        int token = blockIdx.x * 32 + warp * 4 + tk;

        int w = word_x[token];
        for (int i = lane; i < WDIM; i += 32)
            g_x[(size_t)token*LSTM_IN + i] = word_emb[(size_t)w*WDIM + i];

        int cval = (lane < LLQ) ? char_x[(size_t)token*LLQ + lane] : 0;
        int f2 = (lane < FILT) ? lane : 0;

        float best = -1e30f;
        #pragma unroll
        for (int p = 0; p < 12; p++) {
            float s = 0.0f;
            #pragma unroll
            for (int k = 0; k < 3; k++) {
                int q = p + k - 2;
                if (q >= 0 && q < LLQ) {
                    int cq = __shfl_sync(0xffffffffu, cval, q);
                    s += ts[cq*90 + k*FILT + f2];
                }
            }
            best = fmaxf(best, s);
        }
        if (lane < FILT)
            g_x[(size_t)token*LSTM_IN + WDIM + lane] = best + cb;
    }
}

// ---------------- K2: xw GEMM via tf32 mma.sync ----------------
// Block 256 thr (8 warps), tile M=128 x N=80, BK=16. Warp tile 32x40 (2 m16 x 5 n8).
// grid (256, 5, 2). N covered exactly: 5*80 = 400.
#define XW_AS_STRIDE 136   // 136 % 32 == 8 -> conflict-free frag loads
#define XW_BS_STRIDE 104   // 104 % 32 == 8

__global__ void __launch_bounds__(256) k_xw(
    const float* __restrict__ wih_f, const float* __restrict__ bih_f, const float* __restrict__ bhh_f,
    const float* __restrict__ wih_b, const float* __restrict__ bih_b, const float* __restrict__ bhh_b)
{
    __shared__ float As[16*XW_AS_STRIDE];   // [k][m]
    __shared__ float Bs[16*XW_BS_STRIDE];   // [k][n]

    int dir = blockIdx.z;
    const float* wih = dir ? wih_b : wih_f;
    const float* bih = dir ? bih_b : bih_f;
    const float* bhh = dir ? bhh_b : bhh_f;
    float* outp = g_xw[dir];

    int m0 = blockIdx.x * 128;
    int n0 = blockIdx.y * 80;
    int tid = threadIdx.x;
    int warp = tid >> 5;
    int lane = tid & 31;
    int gid = lane >> 2;          // 0..7
    int tig = lane & 3;           // 0..3
    int warpM = (warp >> 1) * 32; // 0,32,64,96
    int warpN = (warp & 1) * 40;  // 0,40

    float acc[2][5][4] = {};

    int sm = tid >> 1;            // 0..127 (m row staged by this thread)
    int skq = (tid & 1) * 8;      // 0 or 8

    for (int k0 = 0; k0 < 144; k0 += 16) {
        // stage A[k][m]
        {
            const float* src = g_x + (size_t)(m0 + sm)*LSTM_IN + k0 + skq;
            #pragma unroll
            for (int i = 0; i < 8; i++) {
                int kg = k0 + skq + i;
                float v = (kg < LSTM_IN) ? src[i] : 0.0f;
                As[(skq + i)*XW_AS_STRIDE + sm] = cvt_tf32(v);
            }
        }
        // stage B[k][n]
        #pragma unroll
        for (int i = tid; i < 80*16; i += 256) {
            int k = i & 15;
            int n = i >> 4;
            int kg = k0 + k;
            float v = (kg < LSTM_IN) ? wih[(size_t)(n0 + n)*LSTM_IN + kg] : 0.0f;
            Bs[k*XW_BS_STRIDE + n] = cvt_tf32(v);
        }
        __syncthreads();

        #pragma unroll
        for (int ks = 0; ks < 2; ks++) {
            int kb = ks * 8;
            float a[2][4];
            #pragma unroll
            for (int mt = 0; mt < 2; mt++) {
                int mb = warpM + mt*16;
                a[mt][0] = As[(kb + tig    )*XW_AS_STRIDE + mb + gid];
                a[mt][1] = As[(kb + tig    )*XW_AS_STRIDE + mb + gid + 8];
                a[mt][2] = As[(kb + tig + 4)*XW_AS_STRIDE + mb + gid];
                a[mt][3] = As[(kb + tig + 4)*XW_AS_STRIDE + mb + gid + 8];
            }
            #pragma unroll
            for (int nt = 0; nt < 5; nt++) {
                float b0 = Bs[(kb + tig    )*XW_BS_STRIDE + warpN + nt*8 + gid];
                float b1 = Bs[(kb + tig + 4)*XW_BS_STRIDE + warpN + nt*8 + gid];
                mma_tf32(acc[0][nt], a[0][0], a[0][1], a[0][2], a[0][3], b0, b1);
                mma_tf32(acc[1][nt], a[1][0], a[1][1], a[1][2], a[1][3], b0, b1);
            }
        }
        __syncthreads();
    }

    // epilogue: D frag c0/c1 = (row gid, cols tig*2, tig*2+1); c2/c3 = row gid+8
    #pragma unroll
    for (int nt = 0; nt < 5; nt++) {
        int n = n0 + warpN + nt*8 + tig*2;
        float bb0 = bih[n]   + bhh[n];
        float bb1 = bih[n+1] + bhh[n+1];
        #pragma unroll
        for (int mt = 0; mt < 2; mt++) {
            int mrow = m0 + warpM + mt*16 + gid;
            *(float2*)&outp[(size_t)mrow*G4 + n] =
                make_float2(acc[mt][nt][0] + bb0, acc[mt][nt][1] + bb1);
            *(float2*)&outp[(size_t)(mrow+8)*G4 + n] =
                make_float2(acc[mt][nt][2] + bb0, acc[mt][nt][3] + bb1);
        }
    }
}

// ---------------- K3: LSTM recurrence — batch-interleaved pipeline ----------------
// 128 blocks (2 dir x 64 batch-pairs), 400 threads, w[50] in regs.
// Phase P: matrix(batch1) || activation(batch0). Phase Q: matrix(batch0,s+1) || act(batch1).
__global__ void __launch_bounds__(400, 1) k_lstm(const float* __restrict__ whh_f,
                                                 const float* __restrict__ whh_b)
{
    __shared__ __align__(16) float h0[HH];
    __shared__ __align__(16) float h1[HH];
    __shared__ float gateA[G4];
    __shared__ float gateB[G4];

    int t   = threadIdx.x;
    int dir = blockIdx.x >> 6;
    int b0  = (blockIdx.x & 63) * 2;

    const float* whh = dir ? whh_b : whh_f;
    const float* xw  = g_xw[dir];

    ull w[50];
    {
        const ulonglong2* row = (const ulonglong2*)(whh + (size_t)t*HH);
        #pragma unroll
        for (int i = 0; i < 25; i++) {
            ulonglong2 v = row[i];
            w[2*i]   = v.x;
            w[2*i+1] = v.y;
        }
    }

    if (t < HH) { h0[t] = 0.0f; h1[t] = 0.0f; }
    float c_reg = 0.0f;       // thread 0..99: cA[j]; thread 100..199: cB[j]
    int j_act = (t < 200) ? (t % HH) : 0;
    __syncthreads();

    const ulonglong2* hp0 = (const ulonglong2*)h0;
    const ulonglong2* hp1 = (const ulonglong2*)h1;

    const float* xpA = xw + (size_t)b0    *SS*G4 + t;
    const float* xpB = xw + (size_t)(b0+1)*SS*G4 + t;
    int s0 = dir ? (SS-1) : 0;
    int sstep = dir ? -1 : 1;

    float xa = xpA[s0*G4];
    float xb = xpB[s0*G4];

    // prologue: matrix A(0)  (h0 == 0)
    {
        ull aE = pack2(xa, 0.0f), aO = 0ULL;
        #pragma unroll
        for (int i = 0; i < 25; i++) {
            ulonglong2 hv = hp0[i];
            aE = ffma2(w[2*i],   hv.x, aE);
            aO = ffma2(w[2*i+1], hv.y, aO);
        }
        float2 e = unpack2(aE), o = unpack2(aO);
        gateA[t] = (e.x + o.x) + (e.y + o.y);
    }
    if (SS > 1) xa = xpA[(s0 + sstep)*G4];
    __syncthreads();

    for (int s = 0; s < SS; s++) {
        int sidx = s0 + s*sstep;

        // ---- Phase P: matrix B(s) + act A(s) ----
        {
            ull aE = pack2(xb, 0.0f), aO = 0ULL;
            #pragma unroll
            for (int i = 0; i < 25; i++) {
                ulonglong2 hv = hp1[i];
                aE = ffma2(w[2*i],   hv.x, aE);
                aO = ffma2(w[2*i+1], hv.y, aO);
            }
            float2 e = unpack2(aE), o = unpack2(aO);
            gateB[t] = (e.x + o.x) + (e.y + o.y);
        }
        if (s + 1 < SS) xb = xpB[(sidx + sstep)*G4];

        if (t < 100) {
            float gi = gateA[j_act], gf = gateA[HH + j_act];
            float gg = gateA[2*HH + j_act], go = gateA[3*HH + j_act];
            float si = sig_hw(gi), sf = sig_hw(gf), so = sig_hw(go);
            c_reg = sf*c_reg + si*tanh_hw(gg);
            float h = so*tanh_hw(c_reg);
            h0[j_act] = h;
            g_hcat[((size_t)b0*SS + sidx)*(2*HH) + dir*HH + j_act] = h;
        }
        __syncthreads();

        // ---- Phase Q: matrix A(s+1) + act B(s) ----
        if (s + 1 < SS) {
            ull aE = pack2(xa, 0.0f), aO = 0ULL;
            #pragma unroll
            for (int i = 0; i < 25; i++) {
                ulonglong2 hv = hp0[i];
                aE = ffma2(w[2*i],   hv.x, aE);
                aO = ffma2(w[2*i+1], hv.y, aO);
            }
            float2 e = unpack2(aE), o = unpack2(aO);
            gateA[t] = (e.x + o.x) + (e.y + o.y);
            if (s + 2 < SS) xa = xpA[(sidx + 2*sstep)*G4];
        }

        if (t >= 100 && t < 200) {
            float gi = gateB[j_act], gf = gateB[HH + j_act];
            float gg = gateB[2*HH + j_act], go = gateB[3*HH + j_act];
            float si = sig_hw(gi), sf = sig_hw(gf), so = sig_hw(go);
            c_reg = sf*c_reg + si*tanh_hw(gg);
            float h = so*tanh_hw(c_reg);
            h1[j_act] = h;
            g_hcat[((size_t)(b0+1)*SS + sidx)*(2*HH) + dir*HH + j_act] = h;
        }
        __syncthreads();
    }
}

// ---------------- K4: emission GEMM ----------------
__global__ void k_emission(const float* __restrict__ proj_w, const float* __restrict__ proj_b)
{
    __shared__ float As[8*68];
    __shared__ float Bs[8*32];
    int tid = threadIdx.x;
    int m0 = blockIdx.x * 64;
    int lr = tid >> 2;
    int lk = (tid & 3) * 2;
    int mbase = (tid >> 5) * 8;
    int n = tid & 31;

    ull acc[4] = {};

    for (int k0 = 0; k0 < 200; k0 += 8) {
        #pragma unroll
        for (int i = 0; i < 2; i++)
            As[(lk+i)*68 + lr] = g_hcat[(size_t)(m0+lr)*200 + k0 + lk + i];
        {
            int kq = tid >> 5, nn = tid & 31;
            Bs[kq*32 + nn] = proj_w[nn*200 + k0 + kq];
        }
        __syncthreads();
        #pragma unroll
        for (int kk = 0; kk < 8; kk++) {
            ulonglong2 aA = *(const ulonglong2*)&As[kk*68 + mbase];
            ulonglong2 aB = *(const ulonglong2*)&As[kk*68 + mbase + 4];
            ull s = splat2(Bs[kk*32 + n]);
            acc[0] = ffma2(aA.x, s, acc[0]);
            acc[1] = ffma2(aA.y, s, acc[1]);
            acc[2] = ffma2(aB.x, s, acc[2]);
            acc[3] = ffma2(aB.y, s, acc[3]);
        }
        __syncthreads();
    }

    float pb = proj_b[n];
    #pragma unroll
    for (int i = 0; i < 4; i++) {
        float2 v = unpack2(acc[i]);
        g_em[(size_t)(m0 + mbase + 2*i    )*TAGS + n] = v.x + pb;
        g_em[(size_t)(m0 + mbase + 2*i + 1)*TAGS + n] = v.y + pb;
    }
}

// ---------------- K5: CRF forward — 4 warps split the i-dimension ----------------
__global__ void k_crf(const float* __restrict__ trans,
                      const int* __restrict__ y, const int* __restrict__ mask)
{
    __shared__ float la_s[TAGS];
    __shared__ float pm[4*TAGS];
    __shared__ float ps[4*TAGS];
    __shared__ float red[128];
    __shared__ float sh_total;

    int b = blockIdx.x;
    int tid = threadIdx.x;
    int j = tid & 31;
    int q = tid >> 5;

    float tr[8];
    #pragma unroll
    for (int ii = 0; ii < 8; ii++) tr[ii] = trans[(8*q + ii)*TAGS + j];

    if (tid < TAGS) la_s[tid] = (tid == STARTT) ? 0.0f : NEGV;
    __syncthreads();

    const float* em = g_em + (size_t)b*SS*TAGS;
    const int* mk = mask + b*SS;

    float e_next = 0.0f;
    int   m_next = 0;
    if (q == 0) { e_next = em[j]; m_next = mk[0]; }

    for (int s = 0; s < SS; s++) {
        float v[8];
        #pragma unroll
        for (int ii = 0; ii < 8; ii++) v[ii] = la_s[8*q + ii] + tr[ii];

        float m4[4];
        #pragma unroll
        for (int ii = 0; ii < 4; ii++) m4[ii] = fmaxf(v[ii], v[ii+4]);
        float m = fmaxf(fmaxf(m4[0], m4[1]), fmaxf(m4[2], m4[3]));

        float ev[8];
        #pragma unroll
        for (int ii = 0; ii < 8; ii++) ev[ii] = __expf(v[ii] - m);
        float sum = ((ev[0]+ev[4]) + (ev[1]+ev[5])) + ((ev[2]+ev[6]) + (ev[3]+ev[7]));

        pm[q*TAGS + j] = m;
        ps[q*TAGS + j] = sum;
        __syncthreads();

        if (q == 0) {
            float e = e_next;
            int mm = m_next;
            if (s + 1 < SS) { e_next = em[(s+1)*TAGS + j]; m_next = mk[s+1]; }
            float m0 = pm[j], m1 = pm[TAGS+j], m2 = pm[2*TAGS+j], m3 = pm[3*TAGS+j];
            float M = fmaxf(fmaxf(m0, m1), fmaxf(m2, m3));
            float S = ps[j]*__expf(m0-M) + ps[TAGS+j]*__expf(m1-M)
                    + ps[2*TAGS+j]*__expf(m2-M) + ps[3*TAGS+j]*__expf(m3-M);
            float la2 = e + M + __logf(S);
            la_s[j] = mm ? la2 : la_s[j];
        }
        __syncthreads();
    }

    if (q == 0) {
        float la = la_s[j] + trans[j*TAGS + ENDT];
        float mv = la;
        #pragma unroll
        for (int o = 16; o > 0; o >>= 1) mv = fmaxf(mv, __shfl_xor_sync(0xffffffffu, mv, o));
        float ex = __expf(la - mv);
        #pragma unroll
        for (int o = 16; o > 0; o >>= 1) ex += __shfl_xor_sync(0xffffffffu, ex, o);
        if (j == 0) sh_total = mv + __logf(ex);
    }

    const int* yb = y + b*SS;
    float sc = 0.0f;
    for (int s = tid; s < SS; s += 128) {
        int cur  = yb[s];
        int prev = s ? yb[s-1] : STARTT;
        float p = em[s*TAGS + cur];
        float tt = trans[prev*TAGS + cur];
        sc += (p + tt) * (float)mk[s];
    }
    red[tid] = sc;
    __syncthreads();
    if (tid < 64) red[tid] += red[tid+64];
    __syncthreads();
    if (tid < 32) {
        float v = red[tid] + red[tid+32];
        #pragma unroll
        for (int o = 16; o > 0; o >>= 1) v += __shfl_xor_sync(0xffffffffu, v, o);
        if (tid == 0) {
            v += trans[yb[SS-1]*TAGS + ENDT];
            g_res[b] = v - sh_total;
        }
    }
}

// ---------------- K6: final reduction ----------------
__global__ void k_final(float* out)
{
    __shared__ float s[BB];
    int t = threadIdx.x;
    s[t] = g_res[t];
    __syncthreads();
    for (int o = 64; o > 0; o >>= 1) {
        if (t < o) s[t] += s[t+o];
        __syncthreads();
    }
    if (t == 0) out[0] = -s[0] / (float)BB;
}

// ---------------- launch ----------------
extern "C" void kernel_launch(void* const* d_in, const int* in_sizes, int n_in,
                              void* d_out, int out_size)
{
    const float* word_emb = (const float*)d_in[0];
    const float* char_emb = (const float*)d_in[1];
    const float* conv_w   = (const float*)d_in[2];
    const float* conv_b   = (const float*)d_in[3];
    const float* wih_f    = (const float*)d_in[4];
    const float* whh_f    = (const float*)d_in[5];
    const float* bih_f    = (const float*)d_in[6];
    const float* bhh_f    = (const float*)d_in[7];
    const float* wih_b    = (const float*)d_in[8];
    const float* whh_b    = (const float*)d_in[9];
    const float* bih_b    = (const float*)d_in[10];
    const float* bhh_b    = (const float*)d_in[11];
    const float* proj_w   = (const float*)d_in[12];
    const float* proj_b   = (const float*)d_in[13];
    const float* trans    = (const float*)d_in[14];
    const int*   word_x   = (const int*)d_in[15];
    const int*   char_x   = (const int*)d_in[16];
    const int*   y        = (const int*)d_in[17];
    const int*   mask     = (const int*)d_in[18];
    float* out = (float*)d_out;

    k_table<<<100, 90>>>(char_emb, conv_w);
    k_embed<<<BB*SS/32, 256>>>(word_emb, conv_b, word_x, char_x);

    dim3 g2(256, 5, 2);
    k_xw<<<g2, 256>>>(wih_f, bih_f, bhh_f, wih_b, bih_b, bhh_b);

    k_lstm<<<128, 400>>>(whh_f, whh_b);

    k_emission<<<BB*SS/64, 256>>>(proj_w, proj_b);

    k_crf<<<BB, 128>>>(trans, y, mask);

    k_final<<<1, BB>>>(out);
}

// round 12
// speedup vs baseline: 1.4897x; 1.1101x over previous
#include <cuda_runtime.h>
#include <math.h>
#include <stdint.h>

// ---------------- problem constants ----------------
#define BB    128
#define SS    256
#define LLQ   10
#define TAGS  32
#define STARTT 30
#define ENDT   31
#define WDIM  100
#define CDIM  30
#define FILT  30
#define HH    100
#define LSTM_IN 130
#define G4    400
#define NEGV  (-10000.0f)

typedef unsigned long long ull;

// ---------------- scratch ----------------
__device__ float g_T  [100*3*FILT];
__device__ float g_x  [BB*SS*LSTM_IN];
__device__ float g_xw [2][BB*SS*G4];
__device__ float g_hcat[BB*SS*2*HH];
__device__ float g_em [BB*SS*TAGS];
__device__ float g_res[BB];

// ---------------- helpers ----------------
__device__ __forceinline__ float tanh_hw(float x) {
    float y; asm("tanh.approx.f32 %0, %1;" : "=f"(y) : "f"(x)); return y;
}
__device__ __forceinline__ float sig_hw(float x) {
    return fmaf(0.5f, tanh_hw(0.5f*x), 0.5f);
}
__device__ __forceinline__ ull ffma2(ull a, ull b, ull c) {
    ull d;
    asm("fma.rn.f32x2 %0, %1, %2, %3;" : "=l"(d) : "l"(a), "l"(b), "l"(c));
    return d;
}
__device__ __forceinline__ ull splat2(float x) {
    ull d; asm("mov.b64 %0, {%1, %1};" : "=l"(d) : "f"(x)); return d;
}
__device__ __forceinline__ ull pack2(float lo, float hi) {
    ull d; asm("mov.b64 %0, {%1, %2};" : "=l"(d) : "f"(lo), "f"(hi)); return d;
}
__device__ __forceinline__ float2 unpack2(ull v) {
    float2 r; asm("mov.b64 {%0, %1}, %2;" : "=f"(r.x), "=f"(r.y) : "l"(v)); return r;
}
__device__ __forceinline__ float cvt_tf32(float x) {
    uint32_t u;
    asm("cvt.rna.tf32.f32 %0, %1;" : "=r"(u) : "f"(x));
    return __uint_as_float(u);
}
__device__ __forceinline__ void mma_tf32(float* c,
                                         float a0, float a1, float a2, float a3,
                                         float b0, float b1) {
    asm("mma.sync.aligned.m16n8k8.row.col.f32.tf32.tf32.f32 "
        "{%0,%1,%2,%3}, {%4,%5,%6,%7}, {%8,%9}, {%0,%1,%2,%3};"
        : "+f"(c[0]), "+f"(c[1]), "+f"(c[2]), "+f"(c[3])
        : "r"(__float_as_uint(a0)), "r"(__float_as_uint(a1)),
          "r"(__float_as_uint(a2)), "r"(__float_as_uint(a3)),
          "r"(__float_as_uint(b0)), "r"(__float_as_uint(b1)));
}

// ---------------- K0: conv table ----------------
__global__ void k_table(const float* __restrict__ char_emb,
                        const float* __restrict__ conv_w)
{
    __shared__ float ce[CDIM];
    int c = blockIdx.x;
    int t = threadIdx.x;
    if (t < CDIM) ce[t] = char_emb[c*CDIM + t];
    __syncthreads();
    int k = t / FILT, f = t % FILT;
    float s = 0.0f;
    #pragma unroll
    for (int d = 0; d < CDIM; d++) s += ce[d] * conv_w[f*90 + k*CDIM + d];
    g_T[c*90 + k*FILT + f] = s;
}

// ---------------- K1: word-emb gather + char maxpool (32 tokens/block) ----------------
__global__ void k_embed(const float* __restrict__ word_emb,
                        const float* __restrict__ conv_b,
                        const int*   __restrict__ word_x,
                        const int*   __restrict__ char_x)
{
    __shared__ float ts[9000];
    int tid = threadIdx.x;
    for (int i = tid; i < 9000; i += 256) ts[i] = g_T[i];
    __syncthreads();

    int lane = tid & 31;
    int warp = tid >> 5;
    float cb = (lane < FILT) ? conv_b[lane] : 0.0f;

    #pragma unroll
    for (int tk = 0; tk < 4; tk++) {
        int token = blockIdx.x * 32 + warp * 4 + tk;

        int w = word_x[token];
        for (int i = lane; i < WDIM; i += 32)
            g_x[(size_t)token*LSTM_IN + i] = word_emb[(size_t)w*WDIM + i];

        int cval = (lane < LLQ) ? char_x[(size_t)token*LLQ + lane] : 0;
        int f2 = (lane < FILT) ? lane : 0;

        float best = -1e30f;
        #pragma unroll
        for (int p = 0; p < 12; p++) {
            float s = 0.0f;
            #pragma unroll
            for (int k = 0; k < 3; k++) {
                int q = p + k - 2;
                if (q >= 0 && q < LLQ) {
                    int cq = __shfl_sync(0xffffffffu, cval, q);
                    s += ts[cq*90 + k*FILT + f2];
                }
            }
            best = fmaxf(best, s);
        }
        if (lane < FILT)
            g_x[(size_t)token*LSTM_IN + WDIM + lane] = best + cb;
    }
}

// ---------------- K2: xw GEMM via tf32 mma.sync ----------------
#define XW_AS_STRIDE 136
#define XW_BS_STRIDE 104

__global__ void __launch_bounds__(256) k_xw(
    const float* __restrict__ wih_f, const float* __restrict__ bih_f, const float* __restrict__ bhh_f,
    const float* __restrict__ wih_b, const float* __restrict__ bih_b, const float* __restrict__ bhh_b)
{
    __shared__ float As[16*XW_AS_STRIDE];   // [k][m]
    __shared__ float Bs[16*XW_BS_STRIDE];   // [k][n]

    int dir = blockIdx.z;
    const float* wih = dir ? wih_b : wih_f;
    const float* bih = dir ? bih_b : bih_f;
    const float* bhh = dir ? bhh_b : bhh_f;
    float* outp = g_xw[dir];

    int m0 = blockIdx.x * 128;
    int n0 = blockIdx.y * 80;
    int tid = threadIdx.x;
    int warp = tid >> 5;
    int lane = tid & 31;
    int gid = lane >> 2;
    int tig = lane & 3;
    int warpM = (warp >> 1) * 32;
    int warpN = (warp & 1) * 40;

    float acc[2][5][4] = {};

    int sm = tid >> 1;
    int skq = (tid & 1) * 8;

    for (int k0 = 0; k0 < 144; k0 += 16) {
        {
            const float* src = g_x + (size_t)(m0 + sm)*LSTM_IN + k0 + skq;
            #pragma unroll
            for (int i = 0; i < 8; i++) {
                int kg = k0 + skq + i;
                float v = (kg < LSTM_IN) ? src[i] : 0.0f;
                As[(skq + i)*XW_AS_STRIDE + sm] = cvt_tf32(v);
            }
        }
        #pragma unroll
        for (int i = tid; i < 80*16; i += 256) {
            int k = i & 15;
            int n = i >> 4;
            int kg = k0 + k;
            float v = (kg < LSTM_IN) ? wih[(size_t)(n0 + n)*LSTM_IN + kg] : 0.0f;
            Bs[k*XW_BS_STRIDE + n] = cvt_tf32(v);
        }
        __syncthreads();

        #pragma unroll
        for (int ks = 0; ks < 2; ks++) {
            int kb = ks * 8;
            float a[2][4];
            #pragma unroll
            for (int mt = 0; mt < 2; mt++) {
                int mb = warpM + mt*16;
                a[mt][0] = As[(kb + tig    )*XW_AS_STRIDE + mb + gid];
                a[mt][1] = As[(kb + tig    )*XW_AS_STRIDE + mb + gid + 8];
                a[mt][2] = As[(kb + tig + 4)*XW_AS_STRIDE + mb + gid];
                a[mt][3] = As[(kb + tig + 4)*XW_AS_STRIDE + mb + gid + 8];
            }
            #pragma unroll
            for (int nt = 0; nt < 5; nt++) {
                float b0 = Bs[(kb + tig    )*XW_BS_STRIDE + warpN + nt*8 + gid];
                float b1 = Bs[(kb + tig + 4)*XW_BS_STRIDE + warpN + nt*8 + gid];
                mma_tf32(acc[0][nt], a[0][0], a[0][1], a[0][2], a[0][3], b0, b1);
                mma_tf32(acc[1][nt], a[1][0], a[1][1], a[1][2], a[1][3], b0, b1);
            }
        }
        __syncthreads();
    }

    #pragma unroll
    for (int nt = 0; nt < 5; nt++) {
        int n = n0 + warpN + nt*8 + tig*2;
        float bb0 = bih[n]   + bhh[n];
        float bb1 = bih[n+1] + bhh[n+1];
        #pragma unroll
        for (int mt = 0; mt < 2; mt++) {
            int mrow = m0 + warpM + mt*16 + gid;
            *(float2*)&outp[(size_t)mrow*G4 + n] =
                make_float2(acc[mt][nt][0] + bb0, acc[mt][nt][1] + bb1);
            *(float2*)&outp[(size_t)(mrow+8)*G4 + n] =
                make_float2(acc[mt][nt][2] + bb0, acc[mt][nt][3] + bb1);
        }
    }
}

// ---------------- K3: LSTM recurrence — proven R7 design ----------------
// 128 blocks (2 dir x 64 batch-pairs), 400 threads. Thread t = gate row g.
// whh row (100 floats) in 50 ull registers; FFMA2 even/odd-k partial chains;
// single matrix phase with 4 independent accumulator chains; HW tanh activations.
__global__ void __launch_bounds__(400, 1) k_lstm(const float* __restrict__ whh_f,
                                                 const float* __restrict__ whh_b)
{
    __shared__ __align__(16) float h0[HH];
    __shared__ __align__(16) float h1[HH];
    __shared__ float gate[2*G4];

    int t   = threadIdx.x;
    int dir = blockIdx.x >> 6;
    int b0  = (blockIdx.x & 63) * 2;

    const float* whh = dir ? whh_b : whh_f;
    const float* xw  = g_xw[dir];

    ull w[50];
    {
        const ulonglong2* row = (const ulonglong2*)(whh + (size_t)t*HH);
        #pragma unroll
        for (int i = 0; i < 25; i++) {
            ulonglong2 v = row[i];
            w[2*i]   = v.x;
            w[2*i+1] = v.y;
        }
    }

    if (t < HH) { h0[t] = 0.0f; h1[t] = 0.0f; }
    int r_act = (t < 200) ? (t / HH) : 0;
    int j_act = (t < 200) ? (t % HH) : 0;
    float c_reg = 0.0f;
    __syncthreads();

    const ulonglong2* hp0 = (const ulonglong2*)h0;
    const ulonglong2* hp1 = (const ulonglong2*)h1;

    int s0 = dir ? (SS-1) : 0;
    float xa = xw[((size_t)b0    *SS + s0)*G4 + t];
    float xb = xw[((size_t)(b0+1)*SS + s0)*G4 + t];

    for (int step = 0; step < SS; step++) {
        int sidx = dir ? (SS-1-step) : step;

        ull acc00 = pack2(xa, 0.0f), acc01 = 0ULL;
        ull acc10 = pack2(xb, 0.0f), acc11 = 0ULL;
        #pragma unroll
        for (int i = 0; i < 25; i++) {
            ulonglong2 hv0 = hp0[i];
            ulonglong2 hv1 = hp1[i];
            acc00 = ffma2(w[2*i],   hv0.x, acc00);
            acc01 = ffma2(w[2*i+1], hv0.y, acc01);
            acc10 = ffma2(w[2*i],   hv1.x, acc10);
            acc11 = ffma2(w[2*i+1], hv1.y, acc11);
        }
        if (step + 1 < SS) {
            int snext = dir ? (SS-2-step) : (step+1);
            xa = xw[((size_t)b0    *SS + snext)*G4 + t];
            xb = xw[((size_t)(b0+1)*SS + snext)*G4 + t];
        }

        float2 p0 = unpack2(acc00), q0 = unpack2(acc01);
        float2 p1 = unpack2(acc10), q1 = unpack2(acc11);
        gate[t]      = (p0.x + q0.x) + (p0.y + q0.y);
        gate[G4 + t] = (p1.x + q1.x) + (p1.y + q1.y);
        __syncthreads();

        if (t < 200) {
            const float* gs = gate + r_act*G4;
            float gi = gs[j_act], gf = gs[HH + j_act], gg = gs[2*HH + j_act], go = gs[3*HH + j_act];
            float si = sig_hw(gi), sf = sig_hw(gf), so = sig_hw(go);
            c_reg = sf*c_reg + si*tanh_hw(gg);
            float h = so*tanh_hw(c_reg);
            ((r_act == 0) ? h0 : h1)[j_act] = h;
            g_hcat[((size_t)(b0 + r_act)*SS + sidx)*(2*HH) + dir*HH + j_act] = h;
        }
        __syncthreads();
    }
}

// ---------------- K4: emission GEMM ----------------
__global__ void k_emission(const float* __restrict__ proj_w, const float* __restrict__ proj_b)
{
    __shared__ float As[8*68];
    __shared__ float Bs[8*32];
    int tid = threadIdx.x;
    int m0 = blockIdx.x * 64;
    int lr = tid >> 2;
    int lk = (tid & 3) * 2;
    int mbase = (tid >> 5) * 8;
    int n = tid & 31;

    ull acc[4] = {};

    for (int k0 = 0; k0 < 200; k0 += 8) {
        #pragma unroll
        for (int i = 0; i < 2; i++)
            As[(lk+i)*68 + lr] = g_hcat[(size_t)(m0+lr)*200 + k0 + lk + i];
        {
            int kq = tid >> 5, nn = tid & 31;
            Bs[kq*32 + nn] = proj_w[nn*200 + k0 + kq];
        }
        __syncthreads();
        #pragma unroll
        for (int kk = 0; kk < 8; kk++) {
            ulonglong2 aA = *(const ulonglong2*)&As[kk*68 + mbase];
            ulonglong2 aB = *(const ulonglong2*)&As[kk*68 + mbase + 4];
            ull s = splat2(Bs[kk*32 + n]);
            acc[0] = ffma2(aA.x, s, acc[0]);
            acc[1] = ffma2(aA.y, s, acc[1]);
            acc[2] = ffma2(aB.x, s, acc[2]);
            acc[3] = ffma2(aB.y, s, acc[3]);
        }
        __syncthreads();
    }

    float pb = proj_b[n];
    #pragma unroll
    for (int i = 0; i < 4; i++) {
        float2 v = unpack2(acc[i]);
        g_em[(size_t)(m0 + mbase + 2*i    )*TAGS + n] = v.x + pb;
        g_em[(size_t)(m0 + mbase + 2*i + 1)*TAGS + n] = v.y + pb;
    }
}

// ---------------- K5: CRF forward — 4 warps split the i-dimension ----------------
__global__ void k_crf(const float* __restrict__ trans,
                      const int* __restrict__ y, const int* __restrict__ mask)
{
    __shared__ float la_s[TAGS];
    __shared__ float pm[4*TAGS];
    __shared__ float ps[4*TAGS];
    __shared__ float red[128];
    __shared__ float sh_total;

    int b = blockIdx.x;
    int tid = threadIdx.x;
    int j = tid & 31;
    int q = tid >> 5;

    float tr[8];
    #pragma unroll
    for (int ii = 0; ii < 8; ii++) tr[ii] = trans[(8*q + ii)*TAGS + j];

    if (tid < TAGS) la_s[tid] = (tid == STARTT) ? 0.0f : NEGV;
    __syncthreads();

    const float* em = g_em + (size_t)b*SS*TAGS;
    const int* mk = mask + b*SS;

    float e_next = 0.0f;
    int   m_next = 0;
    if (q == 0) { e_next = em[j]; m_next = mk[0]; }

    for (int s = 0; s < SS; s++) {
        float v[8];
        #pragma unroll
        for (int ii = 0; ii < 8; ii++) v[ii] = la_s[8*q + ii] + tr[ii];

        float m4[4];
        #pragma unroll
        for (int ii = 0; ii < 4; ii++) m4[ii] = fmaxf(v[ii], v[ii+4]);
        float m = fmaxf(fmaxf(m4[0], m4[1]), fmaxf(m4[2], m4[3]));

        float ev[8];
        #pragma unroll
        for (int ii = 0; ii < 8; ii++) ev[ii] = __expf(v[ii] - m);
        float sum = ((ev[0]+ev[4]) + (ev[1]+ev[5])) + ((ev[2]+ev[6]) + (ev[3]+ev[7]));

        pm[q*TAGS + j] = m;
        ps[q*TAGS + j] = sum;
        __syncthreads();

        if (q == 0) {
            float e = e_next;
            int mm = m_next;
            if (s + 1 < SS) { e_next = em[(s+1)*TAGS + j]; m_next = mk[s+1]; }
            float m0 = pm[j], m1 = pm[TAGS+j], m2 = pm[2*TAGS+j], m3 = pm[3*TAGS+j];
            float M = fmaxf(fmaxf(m0, m1), fmaxf(m2, m3));
            float S = ps[j]*__expf(m0-M) + ps[TAGS+j]*__expf(m1-M)
                    + ps[2*TAGS+j]*__expf(m2-M) + ps[3*TAGS+j]*__expf(m3-M);
            float la2 = e + M + __logf(S);
            la_s[j] = mm ? la2 : la_s[j];
        }
        __syncthreads();
    }

    if (q == 0) {
        float la = la_s[j] + trans[j*TAGS + ENDT];
        float mv = la;
        #pragma unroll
        for (int o = 16; o > 0; o >>= 1) mv = fmaxf(mv, __shfl_xor_sync(0xffffffffu, mv, o));
        float ex = __expf(la - mv);
        #pragma unroll
        for (int o = 16; o > 0; o >>= 1) ex += __shfl_xor_sync(0xffffffffu, ex, o);
        if (j == 0) sh_total = mv + __logf(ex);
    }

    const int* yb = y + b*SS;
    float sc = 0.0f;
    for (int s = tid; s < SS; s += 128) {
        int cur  = yb[s];
        int prev = s ? yb[s-1] : STARTT;
        float p = em[s*TAGS + cur];
        float tt = trans[prev*TAGS + cur];
        sc += (p + tt) * (float)mk[s];
    }
    red[tid] = sc;
    __syncthreads();
    if (tid < 64) red[tid] += red[tid+64];
    __syncthreads();
    if (tid < 32) {
        float v = red[tid] + red[tid+32];
        #pragma unroll
        for (int o = 16; o > 0; o >>= 1) v += __shfl_xor_sync(0xffffffffu, v, o);
        if (tid == 0) {
            v += trans[yb[SS-1]*TAGS + ENDT];
            g_res[b] = v - sh_total;
        }
    }
}

// ---------------- K6: final reduction ----------------
__global__ void k_final(float* out)
{
    __shared__ float s[BB];
    int t = threadIdx.x;
    s[t] = g_res[t];
    __syncthreads();
    for (int o = 64; o > 0; o >>= 1) {
        if (t < o) s[t] += s[t+o];
        __syncthreads();
    }
    if (t == 0) out[0] = -s[0] / (float)BB;
}

// ---------------- launch ----------------
extern "C" void kernel_launch(void* const* d_in, const int* in_sizes, int n_in,
                              void* d_out, int out_size)
{
    const float* word_emb = (const float*)d_in[0];
    const float* char_emb = (const float*)d_in[1];
    const float* conv_w   = (const float*)d_in[2];
    const float* conv_b   = (const float*)d_in[3];
    const float* wih_f    = (const float*)d_in[4];
    const float* whh_f    = (const float*)d_in[5];
    const float* bih_f    = (const float*)d_in[6];
    const float* bhh_f    = (const float*)d_in[7];
    const float* wih_b    = (const float*)d_in[8];
    const float* whh_b    = (const float*)d_in[9];
    const float* bih_b    = (const float*)d_in[10];
    const float* bhh_b    = (const float*)d_in[11];
    const float* proj_w   = (const float*)d_in[12];
    const float* proj_b   = (const float*)d_in[13];
    const float* trans    = (const float*)d_in[14];
    const int*   word_x   = (const int*)d_in[15];
    const int*   char_x   = (const int*)d_in[16];
    const int*   y        = (const int*)d_in[17];
    const int*   mask     = (const int*)d_in[18];
    float* out = (float*)d_out;

    k_table<<<100, 90>>>(char_emb, conv_w);
    k_embed<<<BB*SS/32, 256>>>(word_emb, conv_b, word_x, char_x);

    dim3 g2(256, 5, 2);
    k_xw<<<g2, 256>>>(wih_f, bih_f, bhh_f, wih_b, bih_b, bhh_b);

    k_lstm<<<128, 400>>>(whh_f, whh_b);

    k_emission<<<BB*SS/64, 256>>>(proj_w, proj_b);

    k_crf<<<BB, 128>>>(trans, y, mask);

    k_final<<<1, BB>>>(out);
}

// round 13
// speedup vs baseline: 1.5806x; 1.0610x over previous
#include <cuda_runtime.h>
#include <cuda_fp16.h>
#include <math.h>
#include <stdint.h>

// ---------------- problem constants ----------------
#define BB    128
#define SS    256
#define LLQ   10
#define TAGS  32
#define STARTT 30
#define ENDT   31
#define WDIM  100
#define CDIM  30
#define FILT  30
#define HH    100
#define LSTM_IN 130
#define G4    400
#define NEGV  (-10000.0f)

typedef unsigned long long ull;

// ---------------- scratch ----------------
__device__ float  g_T  [100*3*FILT];
__device__ float  g_x  [BB*SS*LSTM_IN];
__device__ __half g_xwh[2][BB*SS*G4];          // fp16 gates (xw + bias)
__device__ float  g_hcat[BB*SS*2*HH];
__device__ float  g_em [BB*SS*TAGS];
__device__ float  g_res[BB];

// ---------------- helpers ----------------
__device__ __forceinline__ float tanh_hw(float x) {
    float y; asm("tanh.approx.f32 %0, %1;" : "=f"(y) : "f"(x)); return y;
}
__device__ __forceinline__ float sig_hw(float x) {
    return fmaf(0.5f, tanh_hw(0.5f*x), 0.5f);
}
__device__ __forceinline__ ull ffma2(ull a, ull b, ull c) {
    ull d;
    asm("fma.rn.f32x2 %0, %1, %2, %3;" : "=l"(d) : "l"(a), "l"(b), "l"(c));
    return d;
}
__device__ __forceinline__ ull splat2(float x) {
    ull d; asm("mov.b64 %0, {%1, %1};" : "=l"(d) : "f"(x)); return d;
}
__device__ __forceinline__ ull pack2(float lo, float hi) {
    ull d; asm("mov.b64 %0, {%1, %2};" : "=l"(d) : "f"(lo), "f"(hi)); return d;
}
__device__ __forceinline__ float2 unpack2(ull v) {
    float2 r; asm("mov.b64 {%0, %1}, %2;" : "=f"(r.x), "=f"(r.y) : "l"(v)); return r;
}
__device__ __forceinline__ float cvt_tf32(float x) {
    uint32_t u;
    asm("cvt.rna.tf32.f32 %0, %1;" : "=r"(u) : "f"(x));
    return __uint_as_float(u);
}
__device__ __forceinline__ void mma_tf32(float* c,
                                         float a0, float a1, float a2, float a3,
                                         float b0, float b1) {
    asm("mma.sync.aligned.m16n8k8.row.col.f32.tf32.tf32.f32 "
        "{%0,%1,%2,%3}, {%4,%5,%6,%7}, {%8,%9}, {%0,%1,%2,%3};"
        : "+f"(c[0]), "+f"(c[1]), "+f"(c[2]), "+f"(c[3])
        : "r"(__float_as_uint(a0)), "r"(__float_as_uint(a1)),
          "r"(__float_as_uint(a2)), "r"(__float_as_uint(a3)),
          "r"(__float_as_uint(b0)), "r"(__float_as_uint(b1)));
}

// ---------------- K0: conv table ----------------
__global__ void k_table(const float* __restrict__ char_emb,
                        const float* __restrict__ conv_w)
{
    __shared__ float ce[CDIM];
    int c = blockIdx.x;
    int t = threadIdx.x;
    if (t < CDIM) ce[t] = char_emb[c*CDIM + t];
    __syncthreads();
    int k = t / FILT, f = t % FILT;
    float s = 0.0f;
    #pragma unroll
    for (int d = 0; d < CDIM; d++) s += ce[d] * conv_w[f*90 + k*CDIM + d];
    g_T[c*90 + k*FILT + f] = s;
}

// ---------------- K1: word-emb gather + char maxpool (32 tokens/block) ----------------
__global__ void k_embed(const float* __restrict__ word_emb,
                        const float* __restrict__ conv_b,
                        const int*   __restrict__ word_x,
                        const int*   __restrict__ char_x)
{
    __shared__ float ts[9000];
    int tid = threadIdx.x;
    for (int i = tid; i < 9000; i += 256) ts[i] = g_T[i];
    __syncthreads();

    int lane = tid & 31;
    int warp = tid >> 5;
    float cb = (lane < FILT) ? conv_b[lane] : 0.0f;

    #pragma unroll
    for (int tk = 0; tk < 4; tk++) {
        int token = blockIdx.x * 32 + warp * 4 + tk;

        int w = word_x[token];
        for (int i = lane; i < WDIM; i += 32)
            g_x[(size_t)token*LSTM_IN + i] = word_emb[(size_t)w*WDIM + i];

        int cval = (lane < LLQ) ? char_x[(size_t)token*LLQ + lane] : 0;
        int f2 = (lane < FILT) ? lane : 0;

        float best = -1e30f;
        #pragma unroll
        for (int p = 0; p < 12; p++) {
            float s = 0.0f;
            #pragma unroll
            for (int k = 0; k < 3; k++) {
                int q = p + k - 2;
                if (q >= 0 && q < LLQ) {
                    int cq = __shfl_sync(0xffffffffu, cval, q);
                    s += ts[cq*90 + k*FILT + f2];
                }
            }
            best = fmaxf(best, s);
        }
        if (lane < FILT)
            g_x[(size_t)token*LSTM_IN + WDIM + lane] = best + cb;
    }
}

// ---------------- K2: xw GEMM via tf32 mma.sync, fp16 output ----------------
#define XW_AS_STRIDE 136
#define XW_BS_STRIDE 104

__global__ void __launch_bounds__(256) k_xw(
    const float* __restrict__ wih_f, const float* __restrict__ bih_f, const float* __restrict__ bhh_f,
    const float* __restrict__ wih_b, const float* __restrict__ bih_b, const float* __restrict__ bhh_b)
{
    __shared__ float As[16*XW_AS_STRIDE];   // [k][m]
    __shared__ float Bs[16*XW_BS_STRIDE];   // [k][n]

    int dir = blockIdx.z;
    const float* wih = dir ? wih_b : wih_f;
    const float* bih = dir ? bih_b : bih_f;
    const float* bhh = dir ? bhh_b : bhh_f;
    __half* outp = g_xwh[dir];

    int m0 = blockIdx.x * 128;
    int n0 = blockIdx.y * 80;
    int tid = threadIdx.x;
    int warp = tid >> 5;
    int lane = tid & 31;
    int gid = lane >> 2;
    int tig = lane & 3;
    int warpM = (warp >> 1) * 32;
    int warpN = (warp & 1) * 40;

    float acc[2][5][4] = {};

    int sm = tid >> 1;
    int skq = (tid & 1) * 8;

    for (int k0 = 0; k0 < 144; k0 += 16) {
        {
            const float* src = g_x + (size_t)(m0 + sm)*LSTM_IN + k0 + skq;
            #pragma unroll
            for (int i = 0; i < 8; i++) {
                int kg = k0 + skq + i;
                float v = (kg < LSTM_IN) ? src[i] : 0.0f;
                As[(skq + i)*XW_AS_STRIDE + sm] = cvt_tf32(v);
            }
        }
        #pragma unroll
        for (int i = tid; i < 80*16; i += 256) {
            int k = i & 15;
            int n = i >> 4;
            int kg = k0 + k;
            float v = (kg < LSTM_IN) ? wih[(size_t)(n0 + n)*LSTM_IN + kg] : 0.0f;
            Bs[k*XW_BS_STRIDE + n] = cvt_tf32(v);
        }
        __syncthreads();

        #pragma unroll
        for (int ks = 0; ks < 2; ks++) {
            int kb = ks * 8;
            float a[2][4];
            #pragma unroll
            for (int mt = 0; mt < 2; mt++) {
                int mb = warpM + mt*16;
                a[mt][0] = As[(kb + tig    )*XW_AS_STRIDE + mb + gid];
                a[mt][1] = As[(kb + tig    )*XW_AS_STRIDE + mb + gid + 8];
                a[mt][2] = As[(kb + tig + 4)*XW_AS_STRIDE + mb + gid];
                a[mt][3] = As[(kb + tig + 4)*XW_AS_STRIDE + mb + gid + 8];
            }
            #pragma unroll
            for (int nt = 0; nt < 5; nt++) {
                float b0 = Bs[(kb + tig    )*XW_BS_STRIDE + warpN + nt*8 + gid];
                float b1 = Bs[(kb + tig + 4)*XW_BS_STRIDE + warpN + nt*8 + gid];
                mma_tf32(acc[0][nt], a[0][0], a[0][1], a[0][2], a[0][3], b0, b1);
                mma_tf32(acc[1][nt], a[1][0], a[1][1], a[1][2], a[1][3], b0, b1);
            }
        }
        __syncthreads();
    }

    #pragma unroll
    for (int nt = 0; nt < 5; nt++) {
        int n = n0 + warpN + nt*8 + tig*2;
        float bb0 = bih[n]   + bhh[n];
        float bb1 = bih[n+1] + bhh[n+1];
        #pragma unroll
        for (int mt = 0; mt < 2; mt++) {
            int mrow = m0 + warpM + mt*16 + gid;
            *(__half2*)&outp[(size_t)mrow*G4 + n] =
                __floats2half2_rn(acc[mt][nt][0] + bb0, acc[mt][nt][1] + bb1);
            *(__half2*)&outp[(size_t)(mrow+8)*G4 + n] =
                __floats2half2_rn(acc[mt][nt][2] + bb0, acc[mt][nt][3] + bb1);
        }
    }
}

// ---------------- K3: LSTM recurrence — R7 core + early prefetch + high-warp act ----
// 128 blocks (2 dir x 64 batch-pairs), 400 threads. Thread t = gate row g.
// whh row (100 floats) in 50 ull registers; 4 FFMA2 partial chains; HW tanh.
// xw prefetch for step s+1 issued BEFORE the FFMA loop of step s.
// Activation phase on threads t in [200,400) (high warps, arbiter priority).
__global__ void __launch_bounds__(400, 1) k_lstm(const float* __restrict__ whh_f,
                                                 const float* __restrict__ whh_b)
{
    __shared__ __align__(16) float h0[HH];
    __shared__ __align__(16) float h1[HH];
    __shared__ float gate[2*G4];

    int t   = threadIdx.x;
    int dir = blockIdx.x >> 6;
    int b0  = (blockIdx.x & 63) * 2;

    const float* whh = dir ? whh_b : whh_f;
    const __half* xw = g_xwh[dir];

    ull w[50];
    {
        const ulonglong2* row = (const ulonglong2*)(whh + (size_t)t*HH);
        #pragma unroll
        for (int i = 0; i < 25; i++) {
            ulonglong2 v = row[i];
            w[2*i]   = v.x;
            w[2*i+1] = v.y;
        }
    }

    if (t < HH) { h0[t] = 0.0f; h1[t] = 0.0f; }
    // activation phase: threads 200..399 -> (batch row, cell j)
    int r_act = (t >= 300) ? 1 : 0;
    int j_act = (t >= 200) ? (t - 200 - r_act*HH) : 0;
    float c_reg = 0.0f;
    __syncthreads();

    const ulonglong2* hp0 = (const ulonglong2*)h0;
    const ulonglong2* hp1 = (const ulonglong2*)h1;

    int s0 = dir ? (SS-1) : 0;
    __half xa = xw[((size_t)b0    *SS + s0)*G4 + t];
    __half xb = xw[((size_t)(b0+1)*SS + s0)*G4 + t];

    for (int step = 0; step < SS; step++) {
        int sidx = dir ? (SS-1-step) : step;

        // early prefetch of next step's gate inputs (issued before the FFMA loop)
        __half xa_n = __float2half(0.0f), xb_n = xa_n;
        if (step + 1 < SS) {
            int snext = dir ? (SS-2-step) : (step+1);
            xa_n = xw[((size_t)b0    *SS + snext)*G4 + t];
            xb_n = xw[((size_t)(b0+1)*SS + snext)*G4 + t];
        }

        ull acc00 = pack2(__half2float(xa), 0.0f), acc01 = 0ULL;
        ull acc10 = pack2(__half2float(xb), 0.0f), acc11 = 0ULL;
        #pragma unroll
        for (int i = 0; i < 25; i++) {
            ulonglong2 hv0 = hp0[i];
            ulonglong2 hv1 = hp1[i];
            acc00 = ffma2(w[2*i],   hv0.x, acc00);
            acc01 = ffma2(w[2*i+1], hv0.y, acc01);
            acc10 = ffma2(w[2*i],   hv1.x, acc10);
            acc11 = ffma2(w[2*i+1], hv1.y, acc11);
        }
        xa = xa_n;
        xb = xb_n;

        float2 p0 = unpack2(acc00), q0 = unpack2(acc01);
        float2 p1 = unpack2(acc10), q1 = unpack2(acc11);
        gate[t]      = (p0.x + q0.x) + (p0.y + q0.y);
        gate[G4 + t] = (p1.x + q1.x) + (p1.y + q1.y);
        __syncthreads();

        if (t >= 200) {
            const float* gs = gate + r_act*G4;
            float gi = gs[j_act], gf = gs[HH + j_act], gg = gs[2*HH + j_act], go = gs[3*HH + j_act];
            float si = sig_hw(gi), sf = sig_hw(gf), so = sig_hw(go);
            c_reg = sf*c_reg + si*tanh_hw(gg);
            float h = so*tanh_hw(c_reg);
            ((r_act == 0) ? h0 : h1)[j_act] = h;
            g_hcat[((size_t)(b0 + r_act)*SS + sidx)*(2*HH) + dir*HH + j_act] = h;
        }
        __syncthreads();
    }
}

// ---------------- K4: emission GEMM ----------------
__global__ void k_emission(const float* __restrict__ proj_w, const float* __restrict__ proj_b)
{
    __shared__ float As[8*68];
    __shared__ float Bs[8*32];
    int tid = threadIdx.x;
    int m0 = blockIdx.x * 64;
    int lr = tid >> 2;
    int lk = (tid & 3) * 2;
    int mbase = (tid >> 5) * 8;
    int n = tid & 31;

    ull acc[4] = {};

    for (int k0 = 0; k0 < 200; k0 += 8) {
        #pragma unroll
        for (int i = 0; i < 2; i++)
            As[(lk+i)*68 + lr] = g_hcat[(size_t)(m0+lr)*200 + k0 + lk + i];
        {
            int kq = tid >> 5, nn = tid & 31;
            Bs[kq*32 + nn] = proj_w[nn*200 + k0 + kq];
        }
        __syncthreads();
        #pragma unroll
        for (int kk = 0; kk < 8; kk++) {
            ulonglong2 aA = *(const ulonglong2*)&As[kk*68 + mbase];
            ulonglong2 aB = *(const ulonglong2*)&As[kk*68 + mbase + 4];
            ull s = splat2(Bs[kk*32 + n]);
            acc[0] = ffma2(aA.x, s, acc[0]);
            acc[1] = ffma2(aA.y, s, acc[1]);
            acc[2] = ffma2(aB.x, s, acc[2]);
            acc[3] = ffma2(aB.y, s, acc[3]);
        }
        __syncthreads();
    }

    float pb = proj_b[n];
    #pragma unroll
    for (int i = 0; i < 4; i++) {
        float2 v = unpack2(acc[i]);
        g_em[(size_t)(m0 + mbase + 2*i    )*TAGS + n] = v.x + pb;
        g_em[(size_t)(m0 + mbase + 2*i + 1)*TAGS + n] = v.y + pb;
    }
}

// ---------------- K5: CRF forward — 4 warps split the i-dimension ----------------
__global__ void k_crf(const float* __restrict__ trans,
                      const int* __restrict__ y, const int* __restrict__ mask)
{
    __shared__ float la_s[TAGS];
    __shared__ float pm[4*TAGS];
    __shared__ float ps[4*TAGS];
    __shared__ float red[128];
    __shared__ float sh_total;

    int b = blockIdx.x;
    int tid = threadIdx.x;
    int j = tid & 31;
    int q = tid >> 5;

    float tr[8];
    #pragma unroll
    for (int ii = 0; ii < 8; ii++) tr[ii] = trans[(8*q + ii)*TAGS + j];

    if (tid < TAGS) la_s[tid] = (tid == STARTT) ? 0.0f : NEGV;
    __syncthreads();

    const float* em = g_em + (size_t)b*SS*TAGS;
    const int* mk = mask + b*SS;

    float e_next = 0.0f;
    int   m_next = 0;
    if (q == 0) { e_next = em[j]; m_next = mk[0]; }

    for (int s = 0; s < SS; s++) {
        float v[8];
        #pragma unroll
        for (int ii = 0; ii < 8; ii++) v[ii] = la_s[8*q + ii] + tr[ii];

        float m4[4];
        #pragma unroll
        for (int ii = 0; ii < 4; ii++) m4[ii] = fmaxf(v[ii], v[ii+4]);
        float m = fmaxf(fmaxf(m4[0], m4[1]), fmaxf(m4[2], m4[3]));

        float ev[8];
        #pragma unroll
        for (int ii = 0; ii < 8; ii++) ev[ii] = __expf(v[ii] - m);
        float sum = ((ev[0]+ev[4]) + (ev[1]+ev[5])) + ((ev[2]+ev[6]) + (ev[3]+ev[7]));

        pm[q*TAGS + j] = m;
        ps[q*TAGS + j] = sum;
        __syncthreads();

        if (q == 0) {
            float e = e_next;
            int mm = m_next;
            if (s + 1 < SS) { e_next = em[(s+1)*TAGS + j]; m_next = mk[s+1]; }
            float m0 = pm[j], m1 = pm[TAGS+j], m2 = pm[2*TAGS+j], m3 = pm[3*TAGS+j];
            float M = fmaxf(fmaxf(m0, m1), fmaxf(m2, m3));
            float S = ps[j]*__expf(m0-M) + ps[TAGS+j]*__expf(m1-M)
                    + ps[2*TAGS+j]*__expf(m2-M) + ps[3*TAGS+j]*__expf(m3-M);
            float la2 = e + M + __logf(S);
            la_s[j] = mm ? la2 : la_s[j];
        }
        __syncthreads();
    }

    if (q == 0) {
        float la = la_s[j] + trans[j*TAGS + ENDT];
        float mv = la;
        #pragma unroll
        for (int o = 16; o > 0; o >>= 1) mv = fmaxf(mv, __shfl_xor_sync(0xffffffffu, mv, o));
        float ex = __expf(la - mv);
        #pragma unroll
        for (int o = 16; o > 0; o >>= 1) ex += __shfl_xor_sync(0xffffffffu, ex, o);
        if (j == 0) sh_total = mv + __logf(ex);
    }

    const int* yb = y + b*SS;
    float sc = 0.0f;
    for (int s = tid; s < SS; s += 128) {
        int cur  = yb[s];
        int prev = s ? yb[s-1] : STARTT;
        float p = em[s*TAGS + cur];
        float tt = trans[prev*TAGS + cur];
        sc += (p + tt) * (float)mk[s];
    }
    red[tid] = sc;
    __syncthreads();
    if (tid < 64) red[tid] += red[tid+64];
    __syncthreads();
    if (tid < 32) {
        float v = red[tid] + red[tid+32];
        #pragma unroll
        for (int o = 16; o > 0; o >>= 1) v += __shfl_xor_sync(0xffffffffu, v, o);
        if (tid == 0) {
            v += trans[yb[SS-1]*TAGS + ENDT];
            g_res[b] = v - sh_total;
        }
    }
}

// ---------------- K6: final reduction ----------------
__global__ void k_final(float* out)
{
    __shared__ float s[BB];
    int t = threadIdx.x;
    s[t] = g_res[t];
    __syncthreads();
    for (int o = 64; o > 0; o >>= 1) {
        if (t < o) s[t] += s[t+o];
        __syncthreads();
    }
    if (t == 0) out[0] = -s[0] / (float)BB;
}

// ---------------- launch ----------------
extern "C" void kernel_launch(void* const* d_in, const int* in_sizes, int n_in,
                              void* d_out, int out_size)
{
    const float* word_emb = (const float*)d_in[0];
    const float* char_emb = (const float*)d_in[1];
    const float* conv_w   = (const float*)d_in[2];
    const float* conv_b   = (const float*)d_in[3];
    const float* wih_f    = (const float*)d_in[4];
    const float* whh_f    = (const float*)d_in[5];
    const float* bih_f    = (const float*)d_in[6];
    const float* bhh_f    = (const float*)d_in[7];
    const float* wih_b    = (const float*)d_in[8];
    const float* whh_b    = (const float*)d_in[9];
    const float* bih_b    = (const float*)d_in[10];
    const float* bhh_b    = (const float*)d_in[11];
    const float* proj_w   = (const float*)d_in[12];
    const float* proj_b   = (const float*)d_in[13];
    const float* trans    = (const float*)d_in[14];
    const int*   word_x   = (const int*)d_in[15];
    const int*   char_x   = (const int*)d_in[16];
    const int*   y        = (const int*)d_in[17];
    const int*   mask     = (const int*)d_in[18];
    float* out = (float*)d_out;

    k_table<<<100, 90>>>(char_emb, conv_w);
    k_embed<<<BB*SS/32, 256>>>(word_emb, conv_b, word_x, char_x);

    dim3 g2(256, 5, 2);
    k_xw<<<g2, 256>>>(wih_f, bih_f, bhh_f, wih_b, bih_b, bhh_b);

    k_lstm<<<128, 400>>>(whh_f, whh_b);

    k_emission<<<BB*SS/64, 256>>>(proj_w, proj_b);

    k_crf<<<BB, 128>>>(trans, y, mask);

    k_final<<<1, BB>>>(out);
}